// round 9
// baseline (speedup 1.0000x reference)
#include <cuda_runtime.h>
#include <cuda_fp16.h>
#include <math.h>
#include <stdint.h>

#define BATCH 256
#define TLEN  512
#define CIN0  271
#define CH    320
#define NSUBJ 4
#define EPSV  1e-5f
#define PADROWS 516

// ---------------- scratch (__device__ globals; no allocs allowed) ----------
__device__ __align__(16) __half g_hA[(size_t)BATCH * PADROWS * CH];  // 84.5 MB
__device__ __align__(16) __half g_hB[(size_t)BATCH * PADROWS * CH];  // 84.5 MB
__device__ __align__(16) __half g_w[CH * 960];   // [co][KPAD] fp16
__device__ float g_sum[NSUBJ * CH];
__device__ float g_sumsq[NSUBJ * CH];
__device__ float g_scale[NSUBJ * CH];
__device__ float g_shift[NSUBJ * CH];
__device__ int   g_cnt[NSUBJ];

// ---------------- helpers ---------------------------------------------------
__device__ __forceinline__ uint32_t smem_u32(const void* p) {
    uint32_t a;
    asm("{ .reg .u64 t; cvta.to.shared.u64 t, %1; cvt.u32.u64 %0, t; }"
        : "=r"(a) : "l"(p));
    return a;
}
__device__ __forceinline__ void cpasync16(uint32_t s, const void* g) {
    asm volatile("cp.async.cg.shared.global [%0], [%1], 16;" :: "r"(s), "l"(g));
}
#define CP_COMMIT() asm volatile("cp.async.commit_group;" ::: "memory")
#define CP_WAIT2()  asm volatile("cp.async.wait_group 2;" ::: "memory")
#define CP_WAIT1()  asm volatile("cp.async.wait_group 1;" ::: "memory")
#define CP_WAIT0()  asm volatile("cp.async.wait_group 0;" ::: "memory")

#define LDSM_X4(r0, r1, r2, r3, addr) \
    asm volatile("ldmatrix.sync.aligned.m8n8.x4.shared.b16 {%0,%1,%2,%3}, [%4];" \
                 : "=r"(r0), "=r"(r1), "=r"(r2), "=r"(r3) : "r"(addr))

__device__ __forceinline__ void mma_f16(float* d, const uint32_t* a,
                                        uint32_t b0, uint32_t b1) {
    asm volatile(
        "mma.sync.aligned.m16n8k16.row.col.f32.f16.f16.f32 "
        "{%0,%1,%2,%3}, {%4,%5,%6,%7}, {%8,%9}, {%0,%1,%2,%3};"
        : "+f"(d[0]), "+f"(d[1]), "+f"(d[2]), "+f"(d[3])
        : "r"(a[0]), "r"(a[1]), "r"(a[2]), "r"(a[3]), "r"(b0), "r"(b1));
}
__device__ __forceinline__ float gelu_f(float x) {
    return 0.5f * x * (1.0f + erff(x * 0.7071067811865475f));
}

// ------------------------- setup kernels -----------------------------------
__global__ void cb_count(const int* __restrict__ subj) {
    __shared__ int c[NSUBJ];
    int tid = threadIdx.x;
    if (tid < NSUBJ) c[tid] = 0;
    __syncthreads();
    atomicAdd(&c[subj[tid]], 1);
    __syncthreads();
    if (tid < NSUBJ) g_cnt[tid] = c[tid];
}
// Fused init: zero stats, zero pad rows (hA stride-272, hB stride-320),
// transpose+convert w0 -> g_w fp16.
__global__ void cb_init(const float* __restrict__ w0) {
    int i = blockIdx.x * blockDim.x + threadIdx.x;
    const int n0 = 2 * NSUBJ * CH;
    const int n1 = BATCH * 4 * 272;
    const int n2 = BATCH * 4 * 320;
    const int n3 = CH * 832;
    if (i < n0) {
        if (i < NSUBJ * CH) g_sum[i] = 0.f; else g_sumsq[i - NSUBJ * CH] = 0.f;
        return;
    }
    i -= n0;
    if (i < n1) {
        int c = i % 272, rr = (i / 272) & 3, b = i / (4 * 272);
        int row = rr ? 512 + rr : 0;
        g_hA[((size_t)b * PADROWS + row) * 272 + c] = __float2half_rn(0.f);
        return;
    }
    i -= n1;
    if (i < n2) {
        int c = i % 320, rr = (i / 320) & 3, b = i / (4 * 320);
        int row = rr ? 512 + rr : 0;
        g_hB[((size_t)b * PADROWS + row) * 320 + c] = __float2half_rn(0.f);
        return;
    }
    i -= n2;
    if (i < n3) {
        int k = i % 832, co = i / 832;
        int tap = k / 272, ci = k % 272;
        float v = 0.f;
        if (tap < 3 && ci < CIN0) v = w0[((size_t)co * CIN0 + ci) * 3 + tap];
        g_w[(size_t)co * 832 + k] = __float2half_rn(v);
    }
}
// weights [co][cin][3] -> g_w[co][tap*cpad + ci] fp16 (layers 1,2)
__global__ void cb_tw(const float* __restrict__ w, int cin, int cpad, int kpad) {
    int i = blockIdx.x * blockDim.x + threadIdx.x;
    int n = CH * kpad;
    if (i >= n) return;
    int k  = i % kpad;
    int co = i / kpad;
    int tap = k / cpad, ci = k % cpad;
    float v = 0.f;
    if (tap < 3 && ci < cin) v = w[((size_t)co * cin + ci) * 3 + tap];
    g_w[i] = __float2half_rn(v);
}
// X [b][ci][t] fp32 -> g_hA padded NTC fp16 [b][t+1][272] (col 271 zero)
__global__ void cb_xT(const float* __restrict__ X, __half* __restrict__ dst) {
    __shared__ float tile[32][33];
    int lx = threadIdx.x, ly = threadIdx.y;
    int t0 = blockIdx.x * 32, c0 = blockIdx.y * 32, b = blockIdx.z;
#pragma unroll
    for (int i = 0; i < 4; i++) {
        int ci = c0 + ly + i * 8;
        float v = (ci < CIN0) ? X[((size_t)b * CIN0 + ci) * TLEN + t0 + lx] : 0.f;
        tile[ly + i * 8][lx] = v;
    }
    __syncthreads();
#pragma unroll
    for (int i = 0; i < 4; i++) {
        int tr = ly + i * 8;
        int ci = c0 + lx;
        if (ci < 272)
            dst[((size_t)b * PADROWS + t0 + tr + 1) * 272 + ci] =
                __float2half_rn(tile[lx][tr]);
    }
}
// zero pad rows {0,513,514,515} of a padded NTC half buffer of row-width W
__global__ void cb_zero_pads(__half* __restrict__ buf, int W) {
    int i = blockIdx.x * blockDim.x + threadIdx.x;
    int n = BATCH * 4 * W;
    if (i >= n) return;
    int c = i % W;
    int rr = (i / W) & 3;
    int b = i / (4 * W);
    int row = (rr == 0) ? 0 : (512 + rr);
    buf[((size_t)b * PADROWS + row) * W + c] = __float2half_rn(0.f);
}
// finalize scale/shift, then zero the stats for the next layer.
__global__ void cb_finalize(const float* __restrict__ gamma,
                            const float* __restrict__ beta) {
    int i = blockIdx.x * blockDim.x + threadIdx.x;
    if (i >= NSUBJ * CH) return;
    int s = i / CH;
    float cnt  = fmaxf((float)g_cnt[s] * (float)TLEN, 1.0f);
    float mean = g_sum[i] / cnt;
    float var  = g_sumsq[i] / cnt - mean * mean;
    float sc   = gamma[i] * rsqrtf(var + EPSV);
    g_scale[i] = sc;
    g_shift[i] = beta[i] - mean * sc;
    g_sum[i] = 0.f;
    g_sumsq[i] = 0.f;
}
// in-place BN+GELU on padded NTC half buffer rows 1..512 (half2 over channels)
__global__ void cb_bn_gelu(__half* __restrict__ buf, const int* __restrict__ subj) {
    int i = blockIdx.x * blockDim.x + threadIdx.x;
    const int NB = 512 * (CH / 2);
    if (i >= BATCH * NB) return;
    int b = i / NB;
    int rem = i - b * NB;
    int r = rem / (CH / 2);
    int c2 = rem - r * (CH / 2);
    int s = subj[b];
    float2 sc = ((const float2*)g_scale)[s * (CH / 2) + c2];
    float2 sh = ((const float2*)g_shift)[s * (CH / 2) + c2];
    __half2* p = (__half2*)buf + ((size_t)b * PADROWS + r + 1) * (CH / 2) + c2;
    float2 v = __half22float2(*p);
    v.x = gelu_f(fmaf(v.x, sc.x, sh.x));
    v.y = gelu_f(fmaf(v.y, sc.y, sh.y));
    *p = __floats2half2_rn(v.x, v.y);
}
// final: BN+GELU + NTC->NCT transpose into d_out (fp32)
__global__ void cb_out(const __half* __restrict__ buf, const int* __restrict__ subj,
                       float* __restrict__ out) {
    __shared__ float tile[32][33];
    int lx = threadIdx.x, ly = threadIdx.y;
    int t0 = blockIdx.x * 32, c0 = blockIdx.y * 32, b = blockIdx.z;
    int s = subj[b];
    float sc = g_scale[s * CH + c0 + lx];
    float sh = g_shift[s * CH + c0 + lx];
#pragma unroll
    for (int i = 0; i < 4; i++) {
        int tr = ly + i * 8;
        float v = __half2float(buf[((size_t)b * PADROWS + t0 + tr + 1) * CH + c0 + lx]);
        tile[tr][lx] = gelu_f(fmaf(v, sc, sh));
    }
    __syncthreads();
#pragma unroll
    for (int i = 0; i < 4; i++) {
        int cr = ly + i * 8;
        out[((size_t)b * CH + c0 + cr) * TLEN + t0 + lx] = tile[lx][cr];
    }
}

// ------------------------- conv GEMM via mma.sync fp16 + ldmatrix ----------
// A: padded NTC half (row stride CSTRIDE halves). B: g_w [CH][KPAD] half.
// Block: 128 t-rows x 320 co. grid = (4 t, 256 b). 512 threads.
// 4-stage cp.async pipeline, one __syncthreads per 32-k chunk.
// MMA ordering: groups of 5 nf, all-ks0 then all-ks1 (acc RAW distance = 10).
#define NSTAGE 4
#define A_STG (128 * 20)          // u32 per stage
#define B_STG (320 * 20)
#define CONV_SMEM (NSTAGE * (A_STG + B_STG) * 4)
template <int KPAD, int CSTRIDE, bool RES>
__global__ void __launch_bounds__(512, 1) cb_conv(
    const __half* __restrict__ in, const __half* __restrict__ wts,
    const float* __restrict__ bias, const int* __restrict__ subj,
    __half* __restrict__ out)
{
    extern __shared__ uint32_t sm32[];
    uint32_t* As = sm32;                  // [NSTAGE][128][20]
    uint32_t* Bs = sm32 + NSTAGE * A_STG; // [NSTAGE][320][20]
    const uint32_t aB = smem_u32(As);
    const uint32_t bB = smem_u32(Bs);

    const int tid = threadIdx.x;
    const int wid = tid >> 5, lane = tid & 31;
    const int g = lane >> 2, tig = lane & 3;
    const int wm = wid & 3, wn = wid >> 2;
    const int b = blockIdx.y, tBlk = blockIdx.x * 128;
    constexpr int NC = KPAD / 32;

    const __half* Ag = in + ((size_t)b * PADROWS + tBlk) * CSTRIDE;
    const __half* Wg = wts;

    // ldmatrix per-lane base addresses (within a stage, bytes)
    uint32_t aLdsm[2][2];
#pragma unroll
    for (int mf = 0; mf < 2; mf++)
#pragma unroll
        for (int ks = 0; ks < 2; ks++)
            aLdsm[mf][ks] = aB +
                (((wm * 32 + mf * 16 + (lane & 15)) * 20 + ks * 8 + (lane >> 4) * 4) << 2);
    uint32_t bLdsm = bB +
        (((wn * 80 + (lane & 7)) * 20 + (lane >> 3) * 4) << 2);

    // async-copy one 32-k (64B/row) chunk into stage (c % NSTAGE)
    auto issue = [&](int c) {
        const int st = c % NSTAGE;
        const uint32_t ao = aB + st * (A_STG * 4);
        const uint32_t bo = bB + st * (B_STG * 4);
        {   // A: 128 rows x 4 16B segs = 512 ops (1/thread)
            int row = tid >> 2, j = tid & 3;
            cpasync16(ao + row * 80 + j * 16,
                      Ag + (size_t)row * CSTRIDE + c * 32 + j * 8);
        }
        // B: 320 rows x 4 segs = 1280 ops
#pragma unroll
        for (int it = 0; it < 3; it++) {
            int idx = tid + it * 512;
            if (idx < 1280) {
                int row = idx >> 2, j = idx & 3;
                cpasync16(bo + row * 80 + j * 16,
                          Wg + (size_t)row * KPAD + c * 32 + j * 8);
            }
        }
    };

    float acc[2][10][4];
#pragma unroll
    for (int mf = 0; mf < 2; mf++)
#pragma unroll
        for (int nf = 0; nf < 10; nf++)
#pragma unroll
            for (int j = 0; j < 4; j++) acc[mf][nf][j] = 0.f;

    issue(0); CP_COMMIT();
    issue(1); CP_COMMIT();
    issue(2); CP_COMMIT();
    for (int c = 0; c < NC; c++) {
        if (c + 3 <= NC) CP_WAIT2();
        else if (c + 2 == NC) CP_WAIT1();
        else CP_WAIT0();
        __syncthreads();
        if (c + 3 < NC) { issue(c + 3); CP_COMMIT(); }
        const uint32_t stOfs = (c % NSTAGE) * (A_STG * 4);
        const uint32_t stOfsB = (c % NSTAGE) * (B_STG * 4);

        // A fragments for the whole chunk: 4 ldmatrix.x4
        uint32_t af[2][2][4];   // [mf][ks][4]
#pragma unroll
        for (int mf = 0; mf < 2; mf++)
#pragma unroll
            for (int ks = 0; ks < 2; ks++)
                LDSM_X4(af[mf][ks][0], af[mf][ks][1], af[mf][ks][2], af[mf][ks][3],
                        aLdsm[mf][ks] + stOfs);

        // Two groups of 5 nf: LDSM x5, then all ks0 MMAs, then all ks1 MMAs.
#pragma unroll
        for (int gb = 0; gb < 2; gb++) {
            uint32_t bf[5][4];
#pragma unroll
            for (int j = 0; j < 5; j++) {
                int nf = gb * 5 + j;
                LDSM_X4(bf[j][0], bf[j][1], bf[j][2], bf[j][3],
                        bLdsm + stOfsB + nf * (8 * 20 * 4));
            }
#pragma unroll
            for (int j = 0; j < 5; j++) {
                int nf = gb * 5 + j;
                mma_f16(acc[0][nf], af[0][0], bf[j][0], bf[j][1]);
                mma_f16(acc[1][nf], af[1][0], bf[j][0], bf[j][1]);
            }
#pragma unroll
            for (int j = 0; j < 5; j++) {
                int nf = gb * 5 + j;
                mma_f16(acc[0][nf], af[0][1], bf[j][2], bf[j][3]);
                mma_f16(acc[1][nf], af[1][1], bf[j][2], bf[j][3]);
            }
        }
    }

    // Epilogue: bias (+res), store NTC fp16, fused per-subject stats (fp32).
    const int sbj = subj[b];
#pragma unroll
    for (int nf = 0; nf < 10; nf++) {
        const int co = wn * 80 + nf * 8 + 2 * tig;
        const float bv0 = __ldg(bias + co), bv1 = __ldg(bias + co + 1);
        float s0 = 0.f, s1 = 0.f, q0 = 0.f, q1 = 0.f;
#pragma unroll
        for (int mf = 0; mf < 2; mf++) {
            const int trow = tBlk + wm * 32 + mf * 16 + g + 1;
            float y0 = acc[mf][nf][0] + bv0, y1 = acc[mf][nf][1] + bv1;
            float y2 = acc[mf][nf][2] + bv0, y3 = acc[mf][nf][3] + bv1;
            if (RES) {
                float2 r0 = __half22float2(
                    *(const __half2*)(in + ((size_t)b * PADROWS + trow) * CSTRIDE + co));
                float2 r1 = __half22float2(
                    *(const __half2*)(in + ((size_t)b * PADROWS + trow + 8) * CSTRIDE + co));
                y0 += r0.x; y1 += r0.y; y2 += r1.x; y3 += r1.y;
            }
            *(__half2*)(out + ((size_t)b * PADROWS + trow) * CH + co) =
                __floats2half2_rn(y0, y1);
            *(__half2*)(out + ((size_t)b * PADROWS + trow + 8) * CH + co) =
                __floats2half2_rn(y2, y3);
            s0 += y0 + y2; s1 += y1 + y3;
            q0 += y0 * y0 + y2 * y2; q1 += y1 * y1 + y3 * y3;
        }
#pragma unroll
        for (int off = 16; off >= 4; off >>= 1) {
            s0 += __shfl_down_sync(0xffffffffu, s0, off);
            s1 += __shfl_down_sync(0xffffffffu, s1, off);
            q0 += __shfl_down_sync(0xffffffffu, q0, off);
            q1 += __shfl_down_sync(0xffffffffu, q1, off);
        }
        if (lane < 4) {
            atomicAdd(&g_sum[sbj * CH + co], s0);
            atomicAdd(&g_sum[sbj * CH + co + 1], s1);
            atomicAdd(&g_sumsq[sbj * CH + co], q0);
            atomicAdd(&g_sumsq[sbj * CH + co + 1], q1);
        }
    }
}

// ---------------------------------------------------------------------------
extern "C" void kernel_launch(void* const* d_in, const int* in_sizes, int n_in,
                              void* d_out, int out_size) {
    const float* X    = (const float*)d_in[0];
    const int*   subj = (const int*)  d_in[1];
    const float* w0   = (const float*)d_in[2];
    const float* b0   = (const float*)d_in[3];
    const float* w1   = (const float*)d_in[4];
    const float* b1   = (const float*)d_in[5];
    const float* w2   = (const float*)d_in[6];
    const float* b2   = (const float*)d_in[7];
    const float* g0   = (const float*)d_in[8];
    const float* be0  = (const float*)d_in[9];
    const float* g1   = (const float*)d_in[10];
    const float* be1  = (const float*)d_in[11];
    const float* g2   = (const float*)d_in[12];
    const float* be2  = (const float*)d_in[13];
    float* out = (float*)d_out;
    (void)in_sizes; (void)n_in; (void)out_size;

    __half *pA, *pB, *pW;
    cudaGetSymbolAddress((void**)&pA, g_hA);
    cudaGetSymbolAddress((void**)&pB, g_hB);
    cudaGetSymbolAddress((void**)&pW, g_w);

    cudaFuncSetAttribute((const void*)cb_conv<832, 272, false>,
                         cudaFuncAttributeMaxDynamicSharedMemorySize, CONV_SMEM);
    cudaFuncSetAttribute((const void*)cb_conv<960, 320, true>,
                         cudaFuncAttributeMaxDynamicSharedMemorySize, CONV_SMEM);

    const int sgrid = (NSUBJ * CH + 255) / 256;
    const dim3 cgrid(4, BATCH);
    const int bngrid = (BATCH * 512 * (CH / 2) + 255) / 256;
    const int initN = 2 * NSUBJ * CH + BATCH * 4 * 272 + BATCH * 4 * 320 + CH * 832;

    // ---- setup (conv0 lands at launch index 3 for ncu capture) ----
    cb_count<<<1, BATCH>>>(subj);                                   // 0
    cb_init<<<(initN + 511) / 512, 512>>>(w0);                      // 1
    cb_xT<<<dim3(16, 9, BATCH), dim3(32, 8)>>>(X, pA);              // 2

    // ---- layer 0: conv0(hA) -> hB; bn+gelu in place ----
    cb_conv<832, 272, false><<<cgrid, 512, CONV_SMEM>>>(pA, pW, b0, subj, pB); // 3
    cb_zero_pads<<<(BATCH * 4 * CH + 255) / 256, 256>>>(pA, CH);    // hA pads (stride 320)
    cb_finalize<<<sgrid, 256>>>(g0, be0);
    cb_bn_gelu<<<bngrid, 256>>>(pB, subj);

    // ---- layer 1: conv1(hB)+res -> hA; bn+gelu in place ----
    cb_tw<<<(CH * 960 + 255) / 256, 256>>>(w1, CH, CH, 960);
    cb_conv<960, 320, true><<<cgrid, 512, CONV_SMEM>>>(pB, pW, b1, subj, pA);
    cb_finalize<<<sgrid, 256>>>(g1, be1);
    cb_bn_gelu<<<bngrid, 256>>>(pA, subj);

    // ---- layer 2: conv2(hA)+res -> hB; bn+gelu+transpose -> out ----
    cb_tw<<<(CH * 960 + 255) / 256, 256>>>(w2, CH, CH, 960);
    cb_conv<960, 320, true><<<cgrid, 512, CONV_SMEM>>>(pA, pW, b2, subj, pB);
    cb_finalize<<<sgrid, 256>>>(g2, be2);
    cb_out<<<dim3(16, 10, BATCH), dim3(32, 8)>>>(pB, subj, out);
}

// round 10
// speedup vs baseline: 1.0924x; 1.0924x over previous
#include <cuda_runtime.h>
#include <cuda_fp16.h>
#include <math.h>
#include <stdint.h>

#define BATCH 256
#define TLEN  512
#define CIN0  271
#define CH    320
#define NSUBJ 4
#define EPSV  1e-5f
#define PADROWS 516

// ---------------- scratch (__device__ globals; no allocs allowed) ----------
__device__ __align__(16) __half g_hA[(size_t)BATCH * PADROWS * CH];  // 84.5 MB
__device__ __align__(16) __half g_hB[(size_t)BATCH * PADROWS * CH];  // 84.5 MB
__device__ __align__(16) __half g_w[CH * 960];   // [co][KPAD] fp16
__device__ float g_sum[NSUBJ * CH];
__device__ float g_sumsq[NSUBJ * CH];
__device__ float g_scale[NSUBJ * CH];
__device__ float g_shift[NSUBJ * CH];
__device__ int   g_cnt[NSUBJ];

// ---------------- helpers ---------------------------------------------------
__device__ __forceinline__ uint32_t smem_u32(const void* p) {
    uint32_t a;
    asm("{ .reg .u64 t; cvta.to.shared.u64 t, %1; cvt.u32.u64 %0, t; }"
        : "=r"(a) : "l"(p));
    return a;
}
__device__ __forceinline__ void cpasync16(uint32_t s, const void* g) {
    asm volatile("cp.async.cg.shared.global [%0], [%1], 16;" :: "r"(s), "l"(g));
}
#define CP_COMMIT() asm volatile("cp.async.commit_group;" ::: "memory")
#define CP_WAIT2()  asm volatile("cp.async.wait_group 2;" ::: "memory")
#define CP_WAIT1()  asm volatile("cp.async.wait_group 1;" ::: "memory")
#define CP_WAIT0()  asm volatile("cp.async.wait_group 0;" ::: "memory")

#define LDSM_X4(r0, r1, r2, r3, addr) \
    asm volatile("ldmatrix.sync.aligned.m8n8.x4.shared.b16 {%0,%1,%2,%3}, [%4];" \
                 : "=r"(r0), "=r"(r1), "=r"(r2), "=r"(r3) : "r"(addr))

__device__ __forceinline__ void mma_f16(float* d, const uint32_t* a,
                                        uint32_t b0, uint32_t b1) {
    asm volatile(
        "mma.sync.aligned.m16n8k16.row.col.f32.f16.f16.f32 "
        "{%0,%1,%2,%3}, {%4,%5,%6,%7}, {%8,%9}, {%0,%1,%2,%3};"
        : "+f"(d[0]), "+f"(d[1]), "+f"(d[2]), "+f"(d[3])
        : "r"(a[0]), "r"(a[1]), "r"(a[2]), "r"(a[3]), "r"(b0), "r"(b1));
}
__device__ __forceinline__ float gelu_f(float x) {
    return 0.5f * x * (1.0f + erff(x * 0.7071067811865475f));
}

// ------------------------- setup kernels -----------------------------------
__global__ void cb_count(const int* __restrict__ subj) {
    __shared__ int c[NSUBJ];
    int tid = threadIdx.x;
    if (tid < NSUBJ) c[tid] = 0;
    __syncthreads();
    atomicAdd(&c[subj[tid]], 1);
    __syncthreads();
    if (tid < NSUBJ) g_cnt[tid] = c[tid];
}
// Fused init: zero stats, zero pad rows (hA stride-272, hB stride-320),
// transpose+convert w0 -> g_w fp16.
__global__ void cb_init(const float* __restrict__ w0) {
    int i = blockIdx.x * blockDim.x + threadIdx.x;
    const int n0 = 2 * NSUBJ * CH;
    const int n1 = BATCH * 4 * 272;
    const int n2 = BATCH * 4 * 320;
    const int n3 = CH * 832;
    if (i < n0) {
        if (i < NSUBJ * CH) g_sum[i] = 0.f; else g_sumsq[i - NSUBJ * CH] = 0.f;
        return;
    }
    i -= n0;
    if (i < n1) {
        int c = i % 272, rr = (i / 272) & 3, b = i / (4 * 272);
        int row = rr ? 512 + rr : 0;
        g_hA[((size_t)b * PADROWS + row) * 272 + c] = __float2half_rn(0.f);
        return;
    }
    i -= n1;
    if (i < n2) {
        int c = i % 320, rr = (i / 320) & 3, b = i / (4 * 320);
        int row = rr ? 512 + rr : 0;
        g_hB[((size_t)b * PADROWS + row) * 320 + c] = __float2half_rn(0.f);
        return;
    }
    i -= n2;
    if (i < n3) {
        int k = i % 832, co = i / 832;
        int tap = k / 272, ci = k % 272;
        float v = 0.f;
        if (tap < 3 && ci < CIN0) v = w0[((size_t)co * CIN0 + ci) * 3 + tap];
        g_w[(size_t)co * 832 + k] = __float2half_rn(v);
    }
}
// weights [co][cin][3] -> g_w[co][tap*cpad + ci] fp16 (layers 1,2)
__global__ void cb_tw(const float* __restrict__ w, int cin, int cpad, int kpad) {
    int i = blockIdx.x * blockDim.x + threadIdx.x;
    int n = CH * kpad;
    if (i >= n) return;
    int k  = i % kpad;
    int co = i / kpad;
    int tap = k / cpad, ci = k % cpad;
    float v = 0.f;
    if (tap < 3 && ci < cin) v = w[((size_t)co * cin + ci) * 3 + tap];
    g_w[i] = __float2half_rn(v);
}
// X [b][ci][t] fp32 -> g_hA padded NTC fp16 [b][t+1][272] (col 271 zero)
__global__ void cb_xT(const float* __restrict__ X, __half* __restrict__ dst) {
    __shared__ float tile[32][33];
    int lx = threadIdx.x, ly = threadIdx.y;
    int t0 = blockIdx.x * 32, c0 = blockIdx.y * 32, b = blockIdx.z;
#pragma unroll
    for (int i = 0; i < 4; i++) {
        int ci = c0 + ly + i * 8;
        float v = (ci < CIN0) ? X[((size_t)b * CIN0 + ci) * TLEN + t0 + lx] : 0.f;
        tile[ly + i * 8][lx] = v;
    }
    __syncthreads();
#pragma unroll
    for (int i = 0; i < 4; i++) {
        int tr = ly + i * 8;
        int ci = c0 + lx;
        if (ci < 272)
            dst[((size_t)b * PADROWS + t0 + tr + 1) * 272 + ci] =
                __float2half_rn(tile[lx][tr]);
    }
}
// zero pad rows {0,513,514,515} of a padded NTC half buffer of row-width W
__global__ void cb_zero_pads(__half* __restrict__ buf, int W) {
    int i = blockIdx.x * blockDim.x + threadIdx.x;
    int n = BATCH * 4 * W;
    if (i >= n) return;
    int c = i % W;
    int rr = (i / W) & 3;
    int b = i / (4 * W);
    int row = (rr == 0) ? 0 : (512 + rr);
    buf[((size_t)b * PADROWS + row) * W + c] = __float2half_rn(0.f);
}
// finalize scale/shift, then zero the stats for the next layer.
__global__ void cb_finalize(const float* __restrict__ gamma,
                            const float* __restrict__ beta) {
    int i = blockIdx.x * blockDim.x + threadIdx.x;
    if (i >= NSUBJ * CH) return;
    int s = i / CH;
    float cnt  = fmaxf((float)g_cnt[s] * (float)TLEN, 1.0f);
    float mean = g_sum[i] / cnt;
    float var  = g_sumsq[i] / cnt - mean * mean;
    float sc   = gamma[i] * rsqrtf(var + EPSV);
    g_scale[i] = sc;
    g_shift[i] = beta[i] - mean * sc;
    g_sum[i] = 0.f;
    g_sumsq[i] = 0.f;
}
// in-place BN+GELU on padded NTC half buffer rows 1..512 (half2 over channels)
__global__ void cb_bn_gelu(__half* __restrict__ buf, const int* __restrict__ subj) {
    int i = blockIdx.x * blockDim.x + threadIdx.x;
    const int NB = 512 * (CH / 2);
    if (i >= BATCH * NB) return;
    int b = i / NB;
    int rem = i - b * NB;
    int r = rem / (CH / 2);
    int c2 = rem - r * (CH / 2);
    int s = subj[b];
    float2 sc = ((const float2*)g_scale)[s * (CH / 2) + c2];
    float2 sh = ((const float2*)g_shift)[s * (CH / 2) + c2];
    __half2* p = (__half2*)buf + ((size_t)b * PADROWS + r + 1) * (CH / 2) + c2;
    float2 v = __half22float2(*p);
    v.x = gelu_f(fmaf(v.x, sc.x, sh.x));
    v.y = gelu_f(fmaf(v.y, sc.y, sh.y));
    *p = __floats2half2_rn(v.x, v.y);
}
// final: BN+GELU + NTC->NCT transpose into d_out (fp32)
__global__ void cb_out(const __half* __restrict__ buf, const int* __restrict__ subj,
                       float* __restrict__ out) {
    __shared__ float tile[32][33];
    int lx = threadIdx.x, ly = threadIdx.y;
    int t0 = blockIdx.x * 32, c0 = blockIdx.y * 32, b = blockIdx.z;
    int s = subj[b];
    float sc = g_scale[s * CH + c0 + lx];
    float sh = g_shift[s * CH + c0 + lx];
#pragma unroll
    for (int i = 0; i < 4; i++) {
        int tr = ly + i * 8;
        float v = __half2float(buf[((size_t)b * PADROWS + t0 + tr + 1) * CH + c0 + lx]);
        tile[tr][lx] = gelu_f(fmaf(v, sc, sh));
    }
    __syncthreads();
#pragma unroll
    for (int i = 0; i < 4; i++) {
        int cr = ly + i * 8;
        out[((size_t)b * CH + c0 + cr) * TLEN + t0 + lx] = tile[lx][cr];
    }
}

// ------------------------- conv GEMM via mma.sync fp16 + ldmatrix ----------
// A: padded NTC half (row stride CSTRIDE halves). B: g_w [CH][KPAD] half.
// Block: 128 t-rows x 160 co, 256 threads, warp grid 4m x 2n (warp tile 32x80).
// grid = (4 t, 2 co, 256 b) = 2048 blocks, 2 CTAs/SM (32K regs, 92KB smem each).
// 4-stage cp.async pipeline, one __syncthreads per 32-k chunk.
#define TILE_N 160
#define NSTAGE 4
#define A_STG (128 * 20)            // u32 per stage
#define B_STG (TILE_N * 20)
#define CONV_SMEM (NSTAGE * (A_STG + B_STG) * 4)
template <int KPAD, int CSTRIDE, bool RES>
__global__ void __launch_bounds__(256, 2) cb_conv(
    const __half* __restrict__ in, const __half* __restrict__ wts,
    const float* __restrict__ bias, const int* __restrict__ subj,
    __half* __restrict__ out)
{
    extern __shared__ uint32_t sm32[];
    uint32_t* As = sm32;                  // [NSTAGE][128][20]
    uint32_t* Bs = sm32 + NSTAGE * A_STG; // [NSTAGE][160][20]
    const uint32_t aB = smem_u32(As);
    const uint32_t bB = smem_u32(Bs);

    const int tid = threadIdx.x;
    const int wid = tid >> 5, lane = tid & 31;
    const int g = lane >> 2, tig = lane & 3;
    const int wm = wid & 3, wn = wid >> 2;
    const int b = blockIdx.z, coBase = blockIdx.y * TILE_N, tBlk = blockIdx.x * 128;
    constexpr int NC = KPAD / 32;

    const __half* Ag = in + ((size_t)b * PADROWS + tBlk) * CSTRIDE;
    const __half* Wg = wts + (size_t)coBase * KPAD;

    // ldmatrix per-lane base addresses (within a stage, bytes)
    uint32_t aLdsm[2][2];
#pragma unroll
    for (int mf = 0; mf < 2; mf++)
#pragma unroll
        for (int ks = 0; ks < 2; ks++)
            aLdsm[mf][ks] = aB +
                (((wm * 32 + mf * 16 + (lane & 15)) * 20 + ks * 8 + (lane >> 4) * 4) << 2);
    uint32_t bLdsm = bB +
        (((wn * 80 + (lane & 7)) * 20 + (lane >> 3) * 4) << 2);

    // async-copy one 32-k (64B/row) chunk into stage (c % NSTAGE)
    auto issue = [&](int c) {
        const int st = c % NSTAGE;
        const uint32_t ao = aB + st * (A_STG * 4);
        const uint32_t bo = bB + st * (B_STG * 4);
        // A: 128 rows x 4 16B segs = 512 ops (2/thread)
#pragma unroll
        for (int it = 0; it < 2; it++) {
            int idx = tid + it * 256;
            int row = idx >> 2, j = idx & 3;
            cpasync16(ao + row * 80 + j * 16,
                      Ag + (size_t)row * CSTRIDE + c * 32 + j * 8);
        }
        // B: 160 rows x 4 segs = 640 ops
#pragma unroll
        for (int it = 0; it < 3; it++) {
            int idx = tid + it * 256;
            if (idx < 640) {
                int row = idx >> 2, j = idx & 3;
                cpasync16(bo + row * 80 + j * 16,
                          Wg + (size_t)row * KPAD + c * 32 + j * 8);
            }
        }
    };

    float acc[2][10][4];
#pragma unroll
    for (int mf = 0; mf < 2; mf++)
#pragma unroll
        for (int nf = 0; nf < 10; nf++)
#pragma unroll
            for (int j = 0; j < 4; j++) acc[mf][nf][j] = 0.f;

    issue(0); CP_COMMIT();
    issue(1); CP_COMMIT();
    issue(2); CP_COMMIT();
    for (int c = 0; c < NC; c++) {
        if (c + 3 <= NC) CP_WAIT2();
        else if (c + 2 == NC) CP_WAIT1();
        else CP_WAIT0();
        __syncthreads();
        if (c + 3 < NC) { issue(c + 3); CP_COMMIT(); }
        const uint32_t stOfs = (c % NSTAGE) * (A_STG * 4);
        const uint32_t stOfsB = (c % NSTAGE) * (B_STG * 4);

        // A fragments for the whole chunk: 4 ldmatrix.x4
        uint32_t af[2][2][4];   // [mf][ks][4]
#pragma unroll
        for (int mf = 0; mf < 2; mf++)
#pragma unroll
            for (int ks = 0; ks < 2; ks++)
                LDSM_X4(af[mf][ks][0], af[mf][ks][1], af[mf][ks][2], af[mf][ks][3],
                        aLdsm[mf][ks] + stOfs);

#pragma unroll
        for (int nf = 0; nf < 10; nf++) {
            uint32_t bf0, bf1, bf2, bf3;   // {b0,b1} ks0, {b0,b1} ks1
            LDSM_X4(bf0, bf1, bf2, bf3, bLdsm + stOfsB + nf * (8 * 20 * 4));
            mma_f16(acc[0][nf], af[0][0], bf0, bf1);
            mma_f16(acc[1][nf], af[1][0], bf0, bf1);
            mma_f16(acc[0][nf], af[0][1], bf2, bf3);
            mma_f16(acc[1][nf], af[1][1], bf2, bf3);
        }
    }

    // Epilogue: bias (+res), store NTC fp16, fused per-subject stats (fp32).
    const int sbj = subj[b];
#pragma unroll
    for (int nf = 0; nf < 10; nf++) {
        const int co = coBase + wn * 80 + nf * 8 + 2 * tig;
        const float bv0 = __ldg(bias + co), bv1 = __ldg(bias + co + 1);
        float s0 = 0.f, s1 = 0.f, q0 = 0.f, q1 = 0.f;
#pragma unroll
        for (int mf = 0; mf < 2; mf++) {
            const int trow = tBlk + wm * 32 + mf * 16 + g + 1;
            float y0 = acc[mf][nf][0] + bv0, y1 = acc[mf][nf][1] + bv1;
            float y2 = acc[mf][nf][2] + bv0, y3 = acc[mf][nf][3] + bv1;
            if (RES) {
                float2 r0 = __half22float2(
                    *(const __half2*)(in + ((size_t)b * PADROWS + trow) * CSTRIDE + co));
                float2 r1 = __half22float2(
                    *(const __half2*)(in + ((size_t)b * PADROWS + trow + 8) * CSTRIDE + co));
                y0 += r0.x; y1 += r0.y; y2 += r1.x; y3 += r1.y;
            }
            *(__half2*)(out + ((size_t)b * PADROWS + trow) * CH + co) =
                __floats2half2_rn(y0, y1);
            *(__half2*)(out + ((size_t)b * PADROWS + trow + 8) * CH + co) =
                __floats2half2_rn(y2, y3);
            s0 += y0 + y2; s1 += y1 + y3;
            q0 += y0 * y0 + y2 * y2; q1 += y1 * y1 + y3 * y3;
        }
#pragma unroll
        for (int off = 16; off >= 4; off >>= 1) {
            s0 += __shfl_down_sync(0xffffffffu, s0, off);
            s1 += __shfl_down_sync(0xffffffffu, s1, off);
            q0 += __shfl_down_sync(0xffffffffu, q0, off);
            q1 += __shfl_down_sync(0xffffffffu, q1, off);
        }
        if (lane < 4) {
            atomicAdd(&g_sum[sbj * CH + co], s0);
            atomicAdd(&g_sum[sbj * CH + co + 1], s1);
            atomicAdd(&g_sumsq[sbj * CH + co], q0);
            atomicAdd(&g_sumsq[sbj * CH + co + 1], q1);
        }
    }
}

// ---------------------------------------------------------------------------
extern "C" void kernel_launch(void* const* d_in, const int* in_sizes, int n_in,
                              void* d_out, int out_size) {
    const float* X    = (const float*)d_in[0];
    const int*   subj = (const int*)  d_in[1];
    const float* w0   = (const float*)d_in[2];
    const float* b0   = (const float*)d_in[3];
    const float* w1   = (const float*)d_in[4];
    const float* b1   = (const float*)d_in[5];
    const float* w2   = (const float*)d_in[6];
    const float* b2   = (const float*)d_in[7];
    const float* g0   = (const float*)d_in[8];
    const float* be0  = (const float*)d_in[9];
    const float* g1   = (const float*)d_in[10];
    const float* be1  = (const float*)d_in[11];
    const float* g2   = (const float*)d_in[12];
    const float* be2  = (const float*)d_in[13];
    float* out = (float*)d_out;
    (void)in_sizes; (void)n_in; (void)out_size;

    __half *pA, *pB, *pW;
    cudaGetSymbolAddress((void**)&pA, g_hA);
    cudaGetSymbolAddress((void**)&pB, g_hB);
    cudaGetSymbolAddress((void**)&pW, g_w);

    cudaFuncSetAttribute((const void*)cb_conv<832, 272, false>,
                         cudaFuncAttributeMaxDynamicSharedMemorySize, CONV_SMEM);
    cudaFuncSetAttribute((const void*)cb_conv<960, 320, true>,
                         cudaFuncAttributeMaxDynamicSharedMemorySize, CONV_SMEM);

    const int sgrid = (NSUBJ * CH + 255) / 256;
    const dim3 cgrid(4, 2, BATCH);
    const int bngrid = (BATCH * 512 * (CH / 2) + 255) / 256;
    const int initN = 2 * NSUBJ * CH + BATCH * 4 * 272 + BATCH * 4 * 320 + CH * 832;

    // ---- setup (conv0 lands at launch index 3 for ncu capture) ----
    cb_count<<<1, BATCH>>>(subj);                                   // 0
    cb_init<<<(initN + 511) / 512, 512>>>(w0);                      // 1
    cb_xT<<<dim3(16, 9, BATCH), dim3(32, 8)>>>(X, pA);              // 2

    // ---- layer 0: conv0(hA) -> hB; bn+gelu in place ----
    cb_conv<832, 272, false><<<cgrid, 256, CONV_SMEM>>>(pA, pW, b0, subj, pB); // 3
    cb_zero_pads<<<(BATCH * 4 * CH + 255) / 256, 256>>>(pA, CH);    // hA pads (stride 320)
    cb_finalize<<<sgrid, 256>>>(g0, be0);
    cb_bn_gelu<<<bngrid, 256>>>(pB, subj);

    // ---- layer 1: conv1(hB)+res -> hA; bn+gelu in place ----
    cb_tw<<<(CH * 960 + 255) / 256, 256>>>(w1, CH, CH, 960);
    cb_conv<960, 320, true><<<cgrid, 256, CONV_SMEM>>>(pB, pW, b1, subj, pA);
    cb_finalize<<<sgrid, 256>>>(g1, be1);
    cb_bn_gelu<<<bngrid, 256>>>(pA, subj);

    // ---- layer 2: conv2(hA)+res -> hB; bn+gelu+transpose -> out ----
    cb_tw<<<(CH * 960 + 255) / 256, 256>>>(w2, CH, CH, 960);
    cb_conv<960, 320, true><<<cgrid, 256, CONV_SMEM>>>(pA, pW, b2, subj, pB);
    cb_finalize<<<sgrid, 256>>>(g2, be2);
    cb_out<<<dim3(16, 10, BATCH), dim3(32, 8)>>>(pB, subj, out);
}

// round 11
// speedup vs baseline: 1.1802x; 1.0804x over previous
#include <cuda_runtime.h>
#include <cuda_fp16.h>
#include <math.h>
#include <stdint.h>

#define BATCH 256
#define TLEN  512
#define CIN0  271
#define CH    320
#define NSUBJ 4
#define EPSV  1e-5f
#define PADROWS 516

// ---------------- scratch (__device__ globals; no allocs allowed) ----------
__device__ __align__(16) __half g_hA[(size_t)BATCH * PADROWS * CH];  // 84.5 MB
__device__ __align__(16) __half g_hB[(size_t)BATCH * PADROWS * CH];  // 84.5 MB
__device__ __align__(16) __half g_w[CH * 960];   // [co][KPAD] fp16
__device__ float g_sum[NSUBJ * CH];
__device__ float g_sumsq[NSUBJ * CH];
__device__ float g_scale[NSUBJ * CH];
__device__ float g_shift[NSUBJ * CH];
__device__ int   g_cnt[NSUBJ];

// ---------------- helpers ---------------------------------------------------
__device__ __forceinline__ uint32_t smem_u32(const void* p) {
    uint32_t a;
    asm("{ .reg .u64 t; cvta.to.shared.u64 t, %1; cvt.u32.u64 %0, t; }"
        : "=r"(a) : "l"(p));
    return a;
}
__device__ __forceinline__ void cpasync16(uint32_t s, const void* g) {
    asm volatile("cp.async.cg.shared.global [%0], [%1], 16;" :: "r"(s), "l"(g));
}
#define CP_COMMIT() asm volatile("cp.async.commit_group;" ::: "memory")
#define CP_WAIT2()  asm volatile("cp.async.wait_group 2;" ::: "memory")
#define CP_WAIT1()  asm volatile("cp.async.wait_group 1;" ::: "memory")
#define CP_WAIT0()  asm volatile("cp.async.wait_group 0;" ::: "memory")

#define LDSM_X4(r0, r1, r2, r3, addr) \
    asm volatile("ldmatrix.sync.aligned.m8n8.x4.shared.b16 {%0,%1,%2,%3}, [%4];" \
                 : "=r"(r0), "=r"(r1), "=r"(r2), "=r"(r3) : "r"(addr))

__device__ __forceinline__ void mma_f16(float* d, const uint32_t* a,
                                        uint32_t b0, uint32_t b1) {
    asm volatile(
        "mma.sync.aligned.m16n8k16.row.col.f32.f16.f16.f32 "
        "{%0,%1,%2,%3}, {%4,%5,%6,%7}, {%8,%9}, {%0,%1,%2,%3};"
        : "+f"(d[0]), "+f"(d[1]), "+f"(d[2]), "+f"(d[3])
        : "r"(a[0]), "r"(a[1]), "r"(a[2]), "r"(a[3]), "r"(b0), "r"(b1));
}
__device__ __forceinline__ float gelu_f(float x) {
    return 0.5f * x * (1.0f + erff(x * 0.7071067811865475f));
}

// ------------------------- setup kernels -----------------------------------
__global__ void cb_count(const int* __restrict__ subj) {
    __shared__ int c[NSUBJ];
    int tid = threadIdx.x;
    if (tid < NSUBJ) c[tid] = 0;
    __syncthreads();
    atomicAdd(&c[subj[tid]], 1);
    __syncthreads();
    if (tid < NSUBJ) g_cnt[tid] = c[tid];
}
// Fused init: zero stats, zero pad rows (hA stride-272, hB stride-320),
// transpose+convert w0 -> g_w fp16.
__global__ void cb_init(const float* __restrict__ w0) {
    int i = blockIdx.x * blockDim.x + threadIdx.x;
    const int n0 = 2 * NSUBJ * CH;
    const int n1 = BATCH * 4 * 272;
    const int n2 = BATCH * 4 * 320;
    const int n3 = CH * 832;
    if (i < n0) {
        if (i < NSUBJ * CH) g_sum[i] = 0.f; else g_sumsq[i - NSUBJ * CH] = 0.f;
        return;
    }
    i -= n0;
    if (i < n1) {
        int c = i % 272, rr = (i / 272) & 3, b = i / (4 * 272);
        int row = rr ? 512 + rr : 0;
        g_hA[((size_t)b * PADROWS + row) * 272 + c] = __float2half_rn(0.f);
        return;
    }
    i -= n1;
    if (i < n2) {
        int c = i % 320, rr = (i / 320) & 3, b = i / (4 * 320);
        int row = rr ? 512 + rr : 0;
        g_hB[((size_t)b * PADROWS + row) * 320 + c] = __float2half_rn(0.f);
        return;
    }
    i -= n2;
    if (i < n3) {
        int k = i % 832, co = i / 832;
        int tap = k / 272, ci = k % 272;
        float v = 0.f;
        if (tap < 3 && ci < CIN0) v = w0[((size_t)co * CIN0 + ci) * 3 + tap];
        g_w[(size_t)co * 832 + k] = __float2half_rn(v);
    }
}
// X [b][ci][t] fp32 -> g_hA padded NTC fp16 [b][t+1][272] (col 271 zero)
__global__ void cb_xT(const float* __restrict__ X, __half* __restrict__ dst) {
    __shared__ float tile[32][33];
    int lx = threadIdx.x, ly = threadIdx.y;
    int t0 = blockIdx.x * 32, c0 = blockIdx.y * 32, b = blockIdx.z;
#pragma unroll
    for (int i = 0; i < 4; i++) {
        int ci = c0 + ly + i * 8;
        float v = (ci < CIN0) ? X[((size_t)b * CIN0 + ci) * TLEN + t0 + lx] : 0.f;
        tile[ly + i * 8][lx] = v;
    }
    __syncthreads();
#pragma unroll
    for (int i = 0; i < 4; i++) {
        int tr = ly + i * 8;
        int ci = c0 + lx;
        if (ci < 272)
            dst[((size_t)b * PADROWS + t0 + tr + 1) * 272 + ci] =
                __float2half_rn(tile[lx][tr]);
    }
}
// Fused per-layer bookkeeping: finalize scale/shift (+zero stats), optional
// transpose of next layer's weights into g_w, optional pad-row zeroing of the
// next conv's output buffer (stride-320).
__global__ void cb_fin(const float* __restrict__ gamma,
                       const float* __restrict__ beta,
                       const float* __restrict__ wnext,   // may be null
                       __half* __restrict__ padbuf)        // may be null
{
    int i = blockIdx.x * blockDim.x + threadIdx.x;
    const int n0 = NSUBJ * CH;
    const int n1 = CH * 960;
    const int n2 = BATCH * 4 * 320;
    if (i < n0) {
        int s = i / CH;
        float cnt  = fmaxf((float)g_cnt[s] * (float)TLEN, 1.0f);
        float mean = g_sum[i] / cnt;
        float var  = g_sumsq[i] / cnt - mean * mean;
        float sc   = gamma[i] * rsqrtf(var + EPSV);
        g_scale[i] = sc;
        g_shift[i] = beta[i] - mean * sc;
        g_sum[i] = 0.f;
        g_sumsq[i] = 0.f;
        return;
    }
    i -= n0;
    if (i < n1) {
        if (wnext) {
            int k = i % 960, co = i / 960;
            int tap = k / CH, ci = k % CH;
            g_w[i] = __float2half_rn(wnext[((size_t)co * CH + ci) * 3 + tap]);
        }
        return;
    }
    i -= n1;
    if (i < n2 && padbuf) {
        int c = i % 320, rr = (i / 320) & 3, b = i / (4 * 320);
        int row = rr ? 512 + rr : 0;
        padbuf[((size_t)b * PADROWS + row) * 320 + c] = __float2half_rn(0.f);
    }
}
// in-place BN+GELU on padded NTC half buffer rows 1..512; 8 halves per thread.
__global__ void cb_bn_gelu(__half* __restrict__ buf, const int* __restrict__ subj) {
    int i = blockIdx.x * blockDim.x + threadIdx.x;
    const int PER_B = 512 * 40;           // 40 uint4 per 320-ch row
    if (i >= BATCH * PER_B) return;
    int b = i / PER_B;
    int rem = i - b * PER_B;
    int r = rem / 40, c4 = rem - r * 40;
    int s = subj[b];
    const float* scb = g_scale + s * CH + c4 * 8;
    const float* shb = g_shift + s * CH + c4 * 8;
    float4 sc0 = *(const float4*)scb, sc1 = *(const float4*)(scb + 4);
    float4 sh0 = *(const float4*)shb, sh1 = *(const float4*)(shb + 4);
    uint4* p = (uint4*)buf + ((size_t)b * PADROWS + r + 1) * 40 + c4;
    uint4 v = *p;
    __half2* h = (__half2*)&v;
    float2 f0 = __half22float2(h[0]);
    float2 f1 = __half22float2(h[1]);
    float2 f2 = __half22float2(h[2]);
    float2 f3 = __half22float2(h[3]);
    f0.x = gelu_f(fmaf(f0.x, sc0.x, sh0.x));
    f0.y = gelu_f(fmaf(f0.y, sc0.y, sh0.y));
    f1.x = gelu_f(fmaf(f1.x, sc0.z, sh0.z));
    f1.y = gelu_f(fmaf(f1.y, sc0.w, sh0.w));
    f2.x = gelu_f(fmaf(f2.x, sc1.x, sh1.x));
    f2.y = gelu_f(fmaf(f2.y, sc1.y, sh1.y));
    f3.x = gelu_f(fmaf(f3.x, sc1.z, sh1.z));
    f3.y = gelu_f(fmaf(f3.y, sc1.w, sh1.w));
    h[0] = __floats2half2_rn(f0.x, f0.y);
    h[1] = __floats2half2_rn(f1.x, f1.y);
    h[2] = __floats2half2_rn(f2.x, f2.y);
    h[3] = __floats2half2_rn(f3.x, f3.y);
    *p = v;
}
// final: BN+GELU + NTC->NCT transpose into d_out (fp32)
__global__ void cb_out(const __half* __restrict__ buf, const int* __restrict__ subj,
                       float* __restrict__ out) {
    __shared__ float tile[32][33];
    int lx = threadIdx.x, ly = threadIdx.y;
    int t0 = blockIdx.x * 32, c0 = blockIdx.y * 32, b = blockIdx.z;
    int s = subj[b];
    float sc = g_scale[s * CH + c0 + lx];
    float sh = g_shift[s * CH + c0 + lx];
#pragma unroll
    for (int i = 0; i < 4; i++) {
        int tr = ly + i * 8;
        float v = __half2float(buf[((size_t)b * PADROWS + t0 + tr + 1) * CH + c0 + lx]);
        tile[tr][lx] = gelu_f(fmaf(v, sc, sh));
    }
    __syncthreads();
#pragma unroll
    for (int i = 0; i < 4; i++) {
        int cr = ly + i * 8;
        out[((size_t)b * CH + c0 + cr) * TLEN + t0 + lx] = tile[lx][cr];
    }
}

// ------------------------- conv GEMM via mma.sync fp16 + ldmatrix ----------
// A: padded NTC half (row stride CSTRIDE halves). B: g_w [CH][KPAD] half.
// Block: 128 t-rows x 160 co, 256 threads, warp grid 4m x 2n (warp tile 32x80).
// grid = (4 t, 2 co, 256 b) = 2048 blocks, 2 CTAs/SM.
// 4-stage cp.async pipeline, one __syncthreads per 32-k chunk.
// B-fragment 1-deep software pipeline inside the chunk.
#define TILE_N 160
#define NSTAGE 4
#define A_STG (128 * 20)            // u32 per stage
#define B_STG (TILE_N * 20)
#define CONV_SMEM (NSTAGE * (A_STG + B_STG) * 4)
template <int KPAD, int CSTRIDE, bool RES>
__global__ void __launch_bounds__(256, 2) cb_conv(
    const __half* __restrict__ in, const __half* __restrict__ wts,
    const float* __restrict__ bias, const int* __restrict__ subj,
    __half* __restrict__ out)
{
    extern __shared__ uint32_t sm32[];
    uint32_t* As = sm32;                  // [NSTAGE][128][20]
    uint32_t* Bs = sm32 + NSTAGE * A_STG; // [NSTAGE][160][20]
    const uint32_t aB = smem_u32(As);
    const uint32_t bB = smem_u32(Bs);

    const int tid = threadIdx.x;
    const int wid = tid >> 5, lane = tid & 31;
    const int g = lane >> 2, tig = lane & 3;
    const int wm = wid & 3, wn = wid >> 2;
    const int b = blockIdx.z, coBase = blockIdx.y * TILE_N, tBlk = blockIdx.x * 128;
    constexpr int NC = KPAD / 32;

    const __half* Ag = in + ((size_t)b * PADROWS + tBlk) * CSTRIDE;
    const __half* Wg = wts + (size_t)coBase * KPAD;

    // ldmatrix per-lane base addresses (within a stage, bytes)
    uint32_t aLdsm[2][2];
#pragma unroll
    for (int mf = 0; mf < 2; mf++)
#pragma unroll
        for (int ks = 0; ks < 2; ks++)
            aLdsm[mf][ks] = aB +
                (((wm * 32 + mf * 16 + (lane & 15)) * 20 + ks * 8 + (lane >> 4) * 4) << 2);
    uint32_t bLdsm = bB +
        (((wn * 80 + (lane & 7)) * 20 + (lane >> 3) * 4) << 2);

    // async-copy one 32-k (64B/row) chunk into stage (c % NSTAGE)
    auto issue = [&](int c) {
        const int st = c % NSTAGE;
        const uint32_t ao = aB + st * (A_STG * 4);
        const uint32_t bo = bB + st * (B_STG * 4);
        // A: 128 rows x 4 16B segs = 512 ops (2/thread)
#pragma unroll
        for (int it = 0; it < 2; it++) {
            int idx = tid + it * 256;
            int row = idx >> 2, j = idx & 3;
            cpasync16(ao + row * 80 + j * 16,
                      Ag + (size_t)row * CSTRIDE + c * 32 + j * 8);
        }
        // B: 160 rows x 4 segs = 640 ops
#pragma unroll
        for (int it = 0; it < 3; it++) {
            int idx = tid + it * 256;
            if (idx < 640) {
                int row = idx >> 2, j = idx & 3;
                cpasync16(bo + row * 80 + j * 16,
                          Wg + (size_t)row * KPAD + c * 32 + j * 8);
            }
        }
    };

    float acc[2][10][4];
#pragma unroll
    for (int mf = 0; mf < 2; mf++)
#pragma unroll
        for (int nf = 0; nf < 10; nf++)
#pragma unroll
            for (int j = 0; j < 4; j++) acc[mf][nf][j] = 0.f;

    issue(0); CP_COMMIT();
    issue(1); CP_COMMIT();
    issue(2); CP_COMMIT();
    for (int c = 0; c < NC; c++) {
        if (c + 3 <= NC) CP_WAIT2();
        else if (c + 2 == NC) CP_WAIT1();
        else CP_WAIT0();
        __syncthreads();
        if (c + 3 < NC) { issue(c + 3); CP_COMMIT(); }
        const uint32_t stOfs = (c % NSTAGE) * (A_STG * 4);
        const uint32_t stOfsB = (c % NSTAGE) * (B_STG * 4);

        // A fragments for the whole chunk: 4 ldmatrix.x4
        uint32_t af[2][2][4];   // [mf][ks][4]
#pragma unroll
        for (int mf = 0; mf < 2; mf++)
#pragma unroll
            for (int ks = 0; ks < 2; ks++)
                LDSM_X4(af[mf][ks][0], af[mf][ks][1], af[mf][ks][2], af[mf][ks][3],
                        aLdsm[mf][ks] + stOfs);

        // B fragments: 1-deep software pipeline over nf.
        uint32_t bfn0, bfn1, bfn2, bfn3;
        LDSM_X4(bfn0, bfn1, bfn2, bfn3, bLdsm + stOfsB);
#pragma unroll
        for (int nf = 0; nf < 10; nf++) {
            uint32_t bf0 = bfn0, bf1 = bfn1, bf2 = bfn2, bf3 = bfn3;
            if (nf < 9)
                LDSM_X4(bfn0, bfn1, bfn2, bfn3,
                        bLdsm + stOfsB + (nf + 1) * (8 * 20 * 4));
            mma_f16(acc[0][nf], af[0][0], bf0, bf1);
            mma_f16(acc[1][nf], af[1][0], bf0, bf1);
            mma_f16(acc[0][nf], af[0][1], bf2, bf3);
            mma_f16(acc[1][nf], af[1][1], bf2, bf3);
        }
    }

    // Epilogue: bias (+res), store NTC fp16, fused per-subject stats (fp32).
    const int sbj = subj[b];
#pragma unroll
    for (int nf = 0; nf < 10; nf++) {
        const int co = coBase + wn * 80 + nf * 8 + 2 * tig;
        const float bv0 = __ldg(bias + co), bv1 = __ldg(bias + co + 1);
        float s0 = 0.f, s1 = 0.f, q0 = 0.f, q1 = 0.f;
#pragma unroll
        for (int mf = 0; mf < 2; mf++) {
            const int trow = tBlk + wm * 32 + mf * 16 + g + 1;
            float y0 = acc[mf][nf][0] + bv0, y1 = acc[mf][nf][1] + bv1;
            float y2 = acc[mf][nf][2] + bv0, y3 = acc[mf][nf][3] + bv1;
            if (RES) {
                float2 r0 = __half22float2(
                    *(const __half2*)(in + ((size_t)b * PADROWS + trow) * CSTRIDE + co));
                float2 r1 = __half22float2(
                    *(const __half2*)(in + ((size_t)b * PADROWS + trow + 8) * CSTRIDE + co));
                y0 += r0.x; y1 += r0.y; y2 += r1.x; y3 += r1.y;
            }
            *(__half2*)(out + ((size_t)b * PADROWS + trow) * CH + co) =
                __floats2half2_rn(y0, y1);
            *(__half2*)(out + ((size_t)b * PADROWS + trow + 8) * CH + co) =
                __floats2half2_rn(y2, y3);
            s0 += y0 + y2; s1 += y1 + y3;
            q0 += y0 * y0 + y2 * y2; q1 += y1 * y1 + y3 * y3;
        }
#pragma unroll
        for (int off = 16; off >= 4; off >>= 1) {
            s0 += __shfl_down_sync(0xffffffffu, s0, off);
            s1 += __shfl_down_sync(0xffffffffu, s1, off);
            q0 += __shfl_down_sync(0xffffffffu, q0, off);
            q1 += __shfl_down_sync(0xffffffffu, q1, off);
        }
        if (lane < 4) {
            atomicAdd(&g_sum[sbj * CH + co], s0);
            atomicAdd(&g_sum[sbj * CH + co + 1], s1);
            atomicAdd(&g_sumsq[sbj * CH + co], q0);
            atomicAdd(&g_sumsq[sbj * CH + co + 1], q1);
        }
    }
}

// ---------------------------------------------------------------------------
extern "C" void kernel_launch(void* const* d_in, const int* in_sizes, int n_in,
                              void* d_out, int out_size) {
    const float* X    = (const float*)d_in[0];
    const int*   subj = (const int*)  d_in[1];
    const float* w0   = (const float*)d_in[2];
    const float* b0   = (const float*)d_in[3];
    const float* w1   = (const float*)d_in[4];
    const float* b1   = (const float*)d_in[5];
    const float* w2   = (const float*)d_in[6];
    const float* b2   = (const float*)d_in[7];
    const float* g0   = (const float*)d_in[8];
    const float* be0  = (const float*)d_in[9];
    const float* g1   = (const float*)d_in[10];
    const float* be1  = (const float*)d_in[11];
    const float* g2   = (const float*)d_in[12];
    const float* be2  = (const float*)d_in[13];
    float* out = (float*)d_out;
    (void)in_sizes; (void)n_in; (void)out_size;

    __half *pA, *pB, *pW;
    cudaGetSymbolAddress((void**)&pA, g_hA);
    cudaGetSymbolAddress((void**)&pB, g_hB);
    cudaGetSymbolAddress((void**)&pW, g_w);

    cudaFuncSetAttribute((const void*)cb_conv<832, 272, false>,
                         cudaFuncAttributeMaxDynamicSharedMemorySize, CONV_SMEM);
    cudaFuncSetAttribute((const void*)cb_conv<960, 320, true>,
                         cudaFuncAttributeMaxDynamicSharedMemorySize, CONV_SMEM);

    const dim3 cgrid(4, 2, BATCH);
    const int initN = 2 * NSUBJ * CH + BATCH * 4 * 272 + BATCH * 4 * 320 + CH * 832;
    const int finN  = NSUBJ * CH + CH * 960 + BATCH * 4 * 320;
    const int fingrid = (finN + 255) / 256;
    const int bngrid = (BATCH * 512 * 40 + 255) / 256;

    // ---- setup (conv0 lands at launch index 3 for ncu capture) ----
    cb_count<<<1, BATCH>>>(subj);                                   // 0
    cb_init<<<(initN + 511) / 512, 512>>>(w0);                      // 1
    cb_xT<<<dim3(16, 9, BATCH), dim3(32, 8)>>>(X, pA);              // 2

    // ---- layer 0: conv0(hA) -> hB ----
    cb_conv<832, 272, false><<<cgrid, 256, CONV_SMEM>>>(pA, pW, b0, subj, pB); // 3
    cb_fin<<<fingrid, 256>>>(g0, be0, w1, pA);   // finalize0 + tw(w1) + hA pads
    cb_bn_gelu<<<bngrid, 256>>>(pB, subj);

    // ---- layer 1: conv1(hB)+res -> hA ----
    cb_conv<960, 320, true><<<cgrid, 256, CONV_SMEM>>>(pB, pW, b1, subj, pA);
    cb_fin<<<fingrid, 256>>>(g1, be1, w2, (__half*)nullptr);  // finalize1 + tw(w2)
    cb_bn_gelu<<<bngrid, 256>>>(pA, subj);

    // ---- layer 2: conv2(hA)+res -> hB ----
    cb_conv<960, 320, true><<<cgrid, 256, CONV_SMEM>>>(pA, pW, b2, subj, pB);
    cb_fin<<<fingrid, 256>>>(g2, be2, (const float*)nullptr, (__half*)nullptr);
    cb_out<<<dim3(16, 10, BATCH), dim3(32, 8)>>>(pB, subj, out);
}

// round 12
// speedup vs baseline: 1.3952x; 1.1821x over previous
#include <cuda_runtime.h>
#include <cuda_fp16.h>
#include <math.h>
#include <stdint.h>

#define BATCH 256
#define TLEN  512
#define CIN0  271
#define CH    320
#define NSUBJ 4
#define EPSV  1e-5f
#define PADROWS 516

// ---------------- scratch (__device__ globals; no allocs allowed) ----------
__device__ __align__(16) __half g_hA[(size_t)BATCH * PADROWS * CH];  // 84.5 MB
__device__ __align__(16) __half g_hB[(size_t)BATCH * PADROWS * CH];  // 84.5 MB
__device__ __align__(16) __half g_w[CH * 960];   // [co][KPAD] fp16
__device__ float g_sum[NSUBJ * CH];
__device__ float g_sumsq[NSUBJ * CH];
__device__ float g_scale[NSUBJ * CH];
__device__ float g_shift[NSUBJ * CH];
__device__ int   g_cnt[NSUBJ];

// ---------------- helpers ---------------------------------------------------
__device__ __forceinline__ uint32_t smem_u32(const void* p) {
    uint32_t a;
    asm("{ .reg .u64 t; cvta.to.shared.u64 t, %1; cvt.u32.u64 %0, t; }"
        : "=r"(a) : "l"(p));
    return a;
}
__device__ __forceinline__ void cpasync16(uint32_t s, const void* g) {
    asm volatile("cp.async.cg.shared.global [%0], [%1], 16;" :: "r"(s), "l"(g));
}
#define CP_COMMIT() asm volatile("cp.async.commit_group;" ::: "memory")
#define CP_WAIT1()  asm volatile("cp.async.wait_group 1;" ::: "memory")
#define CP_WAIT0()  asm volatile("cp.async.wait_group 0;" ::: "memory")

#define LDSM_X4(r0, r1, r2, r3, addr) \
    asm volatile("ldmatrix.sync.aligned.m8n8.x4.shared.b16 {%0,%1,%2,%3}, [%4];" \
                 : "=r"(r0), "=r"(r1), "=r"(r2), "=r"(r3) : "r"(addr))

__device__ __forceinline__ void mma_f16(float* d, const uint32_t* a,
                                        uint32_t b0, uint32_t b1) {
    asm volatile(
        "mma.sync.aligned.m16n8k16.row.col.f32.f16.f16.f32 "
        "{%0,%1,%2,%3}, {%4,%5,%6,%7}, {%8,%9}, {%0,%1,%2,%3};"
        : "+f"(d[0]), "+f"(d[1]), "+f"(d[2]), "+f"(d[3])
        : "r"(a[0]), "r"(a[1]), "r"(a[2]), "r"(a[3]), "r"(b0), "r"(b1));
}
__device__ __forceinline__ float gelu_f(float x) {
    return 0.5f * x * (1.0f + erff(x * 0.7071067811865475f));
}

// ------------------------- setup kernels -----------------------------------
__global__ void cb_count(const int* __restrict__ subj) {
    __shared__ int c[NSUBJ];
    int tid = threadIdx.x;
    if (tid < NSUBJ) c[tid] = 0;
    __syncthreads();
    atomicAdd(&c[subj[tid]], 1);
    __syncthreads();
    if (tid < NSUBJ) g_cnt[tid] = c[tid];
}
// Fused init: zero stats, zero pad rows (hA stride-272, hB stride-320),
// transpose+convert w0 -> g_w fp16.
__global__ void cb_init(const float* __restrict__ w0) {
    int i = blockIdx.x * blockDim.x + threadIdx.x;
    const int n0 = 2 * NSUBJ * CH;
    const int n1 = BATCH * 4 * 272;
    const int n2 = BATCH * 4 * 320;
    const int n3 = CH * 832;
    if (i < n0) {
        if (i < NSUBJ * CH) g_sum[i] = 0.f; else g_sumsq[i - NSUBJ * CH] = 0.f;
        return;
    }
    i -= n0;
    if (i < n1) {
        int c = i % 272, rr = (i / 272) & 3, b = i / (4 * 272);
        int row = rr ? 512 + rr : 0;
        g_hA[((size_t)b * PADROWS + row) * 272 + c] = __float2half_rn(0.f);
        return;
    }
    i -= n1;
    if (i < n2) {
        int c = i % 320, rr = (i / 320) & 3, b = i / (4 * 320);
        int row = rr ? 512 + rr : 0;
        g_hB[((size_t)b * PADROWS + row) * 320 + c] = __float2half_rn(0.f);
        return;
    }
    i -= n2;
    if (i < n3) {
        int k = i % 832, co = i / 832;
        int tap = k / 272, ci = k % 272;
        float v = 0.f;
        if (tap < 3 && ci < CIN0) v = w0[((size_t)co * CIN0 + ci) * 3 + tap];
        g_w[(size_t)co * 832 + k] = __float2half_rn(v);
    }
}
// X [b][ci][t] fp32 -> g_hA padded NTC fp16 [b][t+1][272] (col 271 zero)
__global__ void cb_xT(const float* __restrict__ X, __half* __restrict__ dst) {
    __shared__ float tile[32][33];
    int lx = threadIdx.x, ly = threadIdx.y;
    int t0 = blockIdx.x * 32, c0 = blockIdx.y * 32, b = blockIdx.z;
#pragma unroll
    for (int i = 0; i < 4; i++) {
        int ci = c0 + ly + i * 8;
        float v = (ci < CIN0) ? X[((size_t)b * CIN0 + ci) * TLEN + t0 + lx] : 0.f;
        tile[ly + i * 8][lx] = v;
    }
    __syncthreads();
#pragma unroll
    for (int i = 0; i < 4; i++) {
        int tr = ly + i * 8;
        int ci = c0 + lx;
        if (ci < 272)
            dst[((size_t)b * PADROWS + t0 + tr + 1) * 272 + ci] =
                __float2half_rn(tile[lx][tr]);
    }
}
// Fused per-layer bookkeeping: finalize scale/shift (+zero stats), optional
// transpose of next layer's weights into g_w, optional pad-row zeroing of the
// next conv's output buffer (stride-320).
__global__ void cb_fin(const float* __restrict__ gamma,
                       const float* __restrict__ beta,
                       const float* __restrict__ wnext,   // may be null
                       __half* __restrict__ padbuf)        // may be null
{
    int i = blockIdx.x * blockDim.x + threadIdx.x;
    const int n0 = NSUBJ * CH;
    const int n1 = CH * 960;
    const int n2 = BATCH * 4 * 320;
    if (i < n0) {
        int s = i / CH;
        float cnt  = fmaxf((float)g_cnt[s] * (float)TLEN, 1.0f);
        float mean = g_sum[i] / cnt;
        float var  = g_sumsq[i] / cnt - mean * mean;
        float sc   = gamma[i] * rsqrtf(var + EPSV);
        g_scale[i] = sc;
        g_shift[i] = beta[i] - mean * sc;
        g_sum[i] = 0.f;
        g_sumsq[i] = 0.f;
        return;
    }
    i -= n0;
    if (i < n1) {
        if (wnext) {
            int k = i % 960, co = i / 960;
            int tap = k / CH, ci = k % CH;
            g_w[i] = __float2half_rn(wnext[((size_t)co * CH + ci) * 3 + tap]);
        }
        return;
    }
    i -= n1;
    if (i < n2 && padbuf) {
        int c = i % 320, rr = (i / 320) & 3, b = i / (4 * 320);
        int row = rr ? 512 + rr : 0;
        padbuf[((size_t)b * PADROWS + row) * 320 + c] = __float2half_rn(0.f);
    }
}
// in-place BN+GELU on padded NTC half buffer rows 1..512; 8 halves per thread.
__global__ void cb_bn_gelu(__half* __restrict__ buf, const int* __restrict__ subj) {
    int i = blockIdx.x * blockDim.x + threadIdx.x;
    const int PER_B = 512 * 40;           // 40 uint4 per 320-ch row
    if (i >= BATCH * PER_B) return;
    int b = i / PER_B;
    int rem = i - b * PER_B;
    int r = rem / 40, c4 = rem - r * 40;
    int s = subj[b];
    const float* scb = g_scale + s * CH + c4 * 8;
    const float* shb = g_shift + s * CH + c4 * 8;
    float4 sc0 = *(const float4*)scb, sc1 = *(const float4*)(scb + 4);
    float4 sh0 = *(const float4*)shb, sh1 = *(const float4*)(shb + 4);
    uint4* p = (uint4*)buf + ((size_t)b * PADROWS + r + 1) * 40 + c4;
    uint4 v = *p;
    __half2* h = (__half2*)&v;
    float2 f0 = __half22float2(h[0]);
    float2 f1 = __half22float2(h[1]);
    float2 f2 = __half22float2(h[2]);
    float2 f3 = __half22float2(h[3]);
    f0.x = gelu_f(fmaf(f0.x, sc0.x, sh0.x));
    f0.y = gelu_f(fmaf(f0.y, sc0.y, sh0.y));
    f1.x = gelu_f(fmaf(f1.x, sc0.z, sh0.z));
    f1.y = gelu_f(fmaf(f1.y, sc0.w, sh0.w));
    f2.x = gelu_f(fmaf(f2.x, sc1.x, sh1.x));
    f2.y = gelu_f(fmaf(f2.y, sc1.y, sh1.y));
    f3.x = gelu_f(fmaf(f3.x, sc1.z, sh1.z));
    f3.y = gelu_f(fmaf(f3.y, sc1.w, sh1.w));
    h[0] = __floats2half2_rn(f0.x, f0.y);
    h[1] = __floats2half2_rn(f1.x, f1.y);
    h[2] = __floats2half2_rn(f2.x, f2.y);
    h[3] = __floats2half2_rn(f3.x, f3.y);
    *p = v;
}
// final: BN+GELU + NTC->NCT transpose into d_out (fp32)
__global__ void cb_out(const __half* __restrict__ buf, const int* __restrict__ subj,
                       float* __restrict__ out) {
    __shared__ float tile[32][33];
    int lx = threadIdx.x, ly = threadIdx.y;
    int t0 = blockIdx.x * 32, c0 = blockIdx.y * 32, b = blockIdx.z;
    int s = subj[b];
    float sc = g_scale[s * CH + c0 + lx];
    float sh = g_shift[s * CH + c0 + lx];
#pragma unroll
    for (int i = 0; i < 4; i++) {
        int tr = ly + i * 8;
        float v = __half2float(buf[((size_t)b * PADROWS + t0 + tr + 1) * CH + c0 + lx]);
        tile[tr][lx] = gelu_f(fmaf(v, sc, sh));
    }
    __syncthreads();
#pragma unroll
    for (int i = 0; i < 4; i++) {
        int cr = ly + i * 8;
        out[((size_t)b * CH + c0 + cr) * TLEN + t0 + lx] = tile[lx][cr];
    }
}

// ------------------------- conv GEMM via mma.sync fp16 + ldmatrix ----------
// A: padded NTC half (row stride CSTRIDE halves). B: g_w [CH][KPAD] half.
// Block: 128 t-rows x 160 co, 256 threads, warp grid 4m x 2n (warp tile 32x80).
// grid = (4 t, 2 co, 256 b) = 2048 blocks, 2 CTAs/SM.
// K-chunk 64 (two k32 sub-chunks per ONE __syncthreads), 3-stage cp.async
// pipeline. 128B rows with XOR-swizzle (seg ^ (row&7)) — no pad, conflict-free.
#define TILE_N 160
#define NSTAGE 3
#define A_STG_B (128 * 128)         // bytes per stage
#define B_STG_B (TILE_N * 128)
#define CONV_SMEM (NSTAGE * (A_STG_B + B_STG_B))   // 110592
template <int KPAD, int CSTRIDE, bool RES>
__global__ void __launch_bounds__(256, 2) cb_conv(
    const __half* __restrict__ in, const __half* __restrict__ wts,
    const float* __restrict__ bias, const int* __restrict__ subj,
    __half* __restrict__ out)
{
    extern __shared__ char smc[];
    const uint32_t aB = smem_u32(smc);
    const uint32_t bB = aB + NSTAGE * A_STG_B;

    const int tid = threadIdx.x;
    const int wid = tid >> 5, lane = tid & 31;
    const int g = lane >> 2, tig = lane & 3;
    const int wm = wid & 3, wn = wid >> 2;
    const int b = blockIdx.z, coBase = blockIdx.y * TILE_N, tBlk = blockIdx.x * 128;
    constexpr int NC = KPAD / 64;

    const __half* Ag = in + ((size_t)b * PADROWS + tBlk) * CSTRIDE;
    const __half* Wg = wts + (size_t)coBase * KPAD;

    // ldmatrix per-lane constants
    const int arow = wm * 32 + (lane & 15);        // mf adds +16 rows (=2048 B)
    const uint32_t aRowB = aB + arow * 128;
    const uint32_t aswz = (uint32_t)(arow & 7) << 4;
    const int ah = lane >> 4;                      // 0/1 (k-half within 8 halves)
    const int brow = wn * 80 + (lane & 7);
    const uint32_t bRowB = bB + brow * 128;
    const uint32_t bswz = (uint32_t)(brow & 7) << 4;
    const int bj = (lane >> 3) & 3;                // matrix index 0..3

    // async-copy one 64-k (128B/row) chunk into stage (c % NSTAGE)
    auto issue = [&](int c) {
        const int st = c % NSTAGE;
        const uint32_t ao = aB + st * A_STG_B;
        const uint32_t bo = bB + st * B_STG_B;
        // A: 128 rows x 8 16B segs = 1024 ops (4/thread)
#pragma unroll
        for (int it = 0; it < 4; it++) {
            int idx = tid + it * 256;
            int row = idx >> 3, j = idx & 7;
            cpasync16(ao + row * 128 + ((uint32_t)(j ^ (row & 7)) << 4),
                      Ag + (size_t)row * CSTRIDE + c * 64 + j * 8);
        }
        // B: 160 rows x 8 segs = 1280 ops (5/thread)
#pragma unroll
        for (int it = 0; it < 5; it++) {
            int idx = tid + it * 256;
            int row = idx >> 3, j = idx & 7;
            cpasync16(bo + row * 128 + ((uint32_t)(j ^ (row & 7)) << 4),
                      Wg + (size_t)row * KPAD + c * 64 + j * 8);
        }
    };

    float acc[2][10][4];
#pragma unroll
    for (int mf = 0; mf < 2; mf++)
#pragma unroll
        for (int nf = 0; nf < 10; nf++)
#pragma unroll
            for (int j = 0; j < 4; j++) acc[mf][nf][j] = 0.f;

    issue(0); CP_COMMIT();
    issue(1); CP_COMMIT();
    for (int c = 0; c < NC; c++) {
        if (c + 1 < NC) CP_WAIT1(); else CP_WAIT0();
        __syncthreads();
        if (c + 2 < NC) { issue(c + 2); CP_COMMIT(); }
        const uint32_t aSt = (c % NSTAGE) * A_STG_B;
        const uint32_t bSt = (c % NSTAGE) * B_STG_B;

        // two k32 sub-chunks, one barrier
#pragma unroll
        for (int h2 = 0; h2 < 2; h2++) {
            // A fragments: 4 ldmatrix.x4
            uint32_t af[2][2][4];   // [mf][ks][4]
#pragma unroll
            for (int mf = 0; mf < 2; mf++)
#pragma unroll
                for (int ks = 0; ks < 2; ks++) {
                    uint32_t seg = (uint32_t)(h2 * 4 + ks * 2 + ah) << 4;
                    LDSM_X4(af[mf][ks][0], af[mf][ks][1],
                            af[mf][ks][2], af[mf][ks][3],
                            aRowB + aSt + mf * 2048 + (seg ^ aswz));
                }
            // B fragments: 1-deep software pipeline over nf
            const uint32_t bSeg = (uint32_t)(h2 * 4 + bj) << 4;
            const uint32_t bAddr0 = bRowB + bSt + (bSeg ^ bswz);
            uint32_t bfn0, bfn1, bfn2, bfn3;
            LDSM_X4(bfn0, bfn1, bfn2, bfn3, bAddr0);
#pragma unroll
            for (int nf = 0; nf < 10; nf++) {
                uint32_t bf0 = bfn0, bf1 = bfn1, bf2 = bfn2, bf3 = bfn3;
                if (nf < 9)
                    LDSM_X4(bfn0, bfn1, bfn2, bfn3, bAddr0 + (nf + 1) * 1024);
                mma_f16(acc[0][nf], af[0][0], bf0, bf1);
                mma_f16(acc[1][nf], af[1][0], bf0, bf1);
                mma_f16(acc[0][nf], af[0][1], bf2, bf3);
                mma_f16(acc[1][nf], af[1][1], bf2, bf3);
            }
        }
    }

    // Epilogue: bias (+res), store NTC fp16, fused per-subject stats (fp32).
    const int sbj = subj[b];
#pragma unroll
    for (int nf = 0; nf < 10; nf++) {
        const int co = coBase + wn * 80 + nf * 8 + 2 * tig;
        const float bv0 = __ldg(bias + co), bv1 = __ldg(bias + co + 1);
        float s0 = 0.f, s1 = 0.f, q0 = 0.f, q1 = 0.f;
#pragma unroll
        for (int mf = 0; mf < 2; mf++) {
            const int trow = tBlk + wm * 32 + mf * 16 + g + 1;
            float y0 = acc[mf][nf][0] + bv0, y1 = acc[mf][nf][1] + bv1;
            float y2 = acc[mf][nf][2] + bv0, y3 = acc[mf][nf][3] + bv1;
            if (RES) {
                float2 r0 = __half22float2(
                    *(const __half2*)(in + ((size_t)b * PADROWS + trow) * CSTRIDE + co));
                float2 r1 = __half22float2(
                    *(const __half2*)(in + ((size_t)b * PADROWS + trow + 8) * CSTRIDE + co));
                y0 += r0.x; y1 += r0.y; y2 += r1.x; y3 += r1.y;
            }
            *(__half2*)(out + ((size_t)b * PADROWS + trow) * CH + co) =
                __floats2half2_rn(y0, y1);
            *(__half2*)(out + ((size_t)b * PADROWS + trow + 8) * CH + co) =
                __floats2half2_rn(y2, y3);
            s0 += y0 + y2; s1 += y1 + y3;
            q0 += y0 * y0 + y2 * y2; q1 += y1 * y1 + y3 * y3;
        }
#pragma unroll
        for (int off = 16; off >= 4; off >>= 1) {
            s0 += __shfl_down_sync(0xffffffffu, s0, off);
            s1 += __shfl_down_sync(0xffffffffu, s1, off);
            q0 += __shfl_down_sync(0xffffffffu, q0, off);
            q1 += __shfl_down_sync(0xffffffffu, q1, off);
        }
        if (lane < 4) {
            atomicAdd(&g_sum[sbj * CH + co], s0);
            atomicAdd(&g_sum[sbj * CH + co + 1], s1);
            atomicAdd(&g_sumsq[sbj * CH + co], q0);
            atomicAdd(&g_sumsq[sbj * CH + co + 1], q1);
        }
    }
}

// ---------------------------------------------------------------------------
extern "C" void kernel_launch(void* const* d_in, const int* in_sizes, int n_in,
                              void* d_out, int out_size) {
    const float* X    = (const float*)d_in[0];
    const int*   subj = (const int*)  d_in[1];
    const float* w0   = (const float*)d_in[2];
    const float* b0   = (const float*)d_in[3];
    const float* w1   = (const float*)d_in[4];
    const float* b1   = (const float*)d_in[5];
    const float* w2   = (const float*)d_in[6];
    const float* b2   = (const float*)d_in[7];
    const float* g0   = (const float*)d_in[8];
    const float* be0  = (const float*)d_in[9];
    const float* g1   = (const float*)d_in[10];
    const float* be1  = (const float*)d_in[11];
    const float* g2   = (const float*)d_in[12];
    const float* be2  = (const float*)d_in[13];
    float* out = (float*)d_out;
    (void)in_sizes; (void)n_in; (void)out_size;

    __half *pA, *pB, *pW;
    cudaGetSymbolAddress((void**)&pA, g_hA);
    cudaGetSymbolAddress((void**)&pB, g_hB);
    cudaGetSymbolAddress((void**)&pW, g_w);

    cudaFuncSetAttribute((const void*)cb_conv<832, 272, false>,
                         cudaFuncAttributeMaxDynamicSharedMemorySize, CONV_SMEM);
    cudaFuncSetAttribute((const void*)cb_conv<960, 320, true>,
                         cudaFuncAttributeMaxDynamicSharedMemorySize, CONV_SMEM);

    const dim3 cgrid(4, 2, BATCH);
    const int initN = 2 * NSUBJ * CH + BATCH * 4 * 272 + BATCH * 4 * 320 + CH * 832;
    const int finN  = NSUBJ * CH + CH * 960 + BATCH * 4 * 320;
    const int fingrid = (finN + 255) / 256;
    const int bngrid = (BATCH * 512 * 40 + 255) / 256;

    // ---- setup (conv0 lands at launch index 3 for ncu capture) ----
    cb_count<<<1, BATCH>>>(subj);                                   // 0
    cb_init<<<(initN + 511) / 512, 512>>>(w0);                      // 1
    cb_xT<<<dim3(16, 9, BATCH), dim3(32, 8)>>>(X, pA);              // 2

    // ---- layer 0: conv0(hA) -> hB ----
    cb_conv<832, 272, false><<<cgrid, 256, CONV_SMEM>>>(pA, pW, b0, subj, pB); // 3
    cb_fin<<<fingrid, 256>>>(g0, be0, w1, pA);   // finalize0 + tw(w1) + hA pads
    cb_bn_gelu<<<bngrid, 256>>>(pB, subj);

    // ---- layer 1: conv1(hB)+res -> hA ----
    cb_conv<960, 320, true><<<cgrid, 256, CONV_SMEM>>>(pB, pW, b1, subj, pA);
    cb_fin<<<fingrid, 256>>>(g1, be1, w2, (__half*)nullptr);  // finalize1 + tw(w2)
    cb_bn_gelu<<<bngrid, 256>>>(pA, subj);

    // ---- layer 2: conv2(hA)+res -> hB ----
    cb_conv<960, 320, true><<<cgrid, 256, CONV_SMEM>>>(pA, pW, b2, subj, pB);
    cb_fin<<<fingrid, 256>>>(g2, be2, (const float*)nullptr, (__half*)nullptr);
    cb_out<<<dim3(16, 10, BATCH), dim3(32, 8)>>>(pB, subj, out);
}

// round 14
// speedup vs baseline: 1.4343x; 1.0280x over previous
#include <cuda_runtime.h>
#include <cuda_fp16.h>
#include <math.h>
#include <stdint.h>

#define BATCH 256
#define TLEN  512
#define CIN0  271
#define CH    320
#define NSUBJ 4
#define EPSV  1e-5f
#define PADROWS 516

// ---------------- scratch (__device__ globals; no allocs allowed) ----------
__device__ __align__(16) __half g_hA[(size_t)BATCH * PADROWS * CH];  // 84.5 MB
__device__ __align__(16) __half g_hB[(size_t)BATCH * PADROWS * CH];  // 84.5 MB
__device__ __align__(16) __half g_w[CH * 960];   // [co][KPAD] fp16
__device__ float g_sum[NSUBJ * CH];
__device__ float g_sumsq[NSUBJ * CH];
__device__ float g_scale[NSUBJ * CH];
__device__ float g_shift[NSUBJ * CH];
__device__ int   g_cnt[NSUBJ];

// ---------------- helpers ---------------------------------------------------
__device__ __forceinline__ uint32_t smem_u32(const void* p) {
    uint32_t a;
    asm("{ .reg .u64 t; cvta.to.shared.u64 t, %1; cvt.u32.u64 %0, t; }"
        : "=r"(a) : "l"(p));
    return a;
}
__device__ __forceinline__ void cpasync16(uint32_t s, const void* g) {
    asm volatile("cp.async.cg.shared.global [%0], [%1], 16;" :: "r"(s), "l"(g));
}
#define CP_COMMIT() asm volatile("cp.async.commit_group;" ::: "memory")
#define CP_WAIT1()  asm volatile("cp.async.wait_group 1;" ::: "memory")
#define CP_WAIT0()  asm volatile("cp.async.wait_group 0;" ::: "memory")

#define LDSM_X4(r0, r1, r2, r3, addr) \
    asm volatile("ldmatrix.sync.aligned.m8n8.x4.shared.b16 {%0,%1,%2,%3}, [%4];" \
                 : "=r"(r0), "=r"(r1), "=r"(r2), "=r"(r3) : "r"(addr))

__device__ __forceinline__ void mma_f16(float* d, const uint32_t* a,
                                        uint32_t b0, uint32_t b1) {
    asm volatile(
        "mma.sync.aligned.m16n8k16.row.col.f32.f16.f16.f32 "
        "{%0,%1,%2,%3}, {%4,%5,%6,%7}, {%8,%9}, {%0,%1,%2,%3};"
        : "+f"(d[0]), "+f"(d[1]), "+f"(d[2]), "+f"(d[3])
        : "r"(a[0]), "r"(a[1]), "r"(a[2]), "r"(a[3]), "r"(b0), "r"(b1));
}
__device__ __forceinline__ float gelu_f(float x) {
    return 0.5f * x * (1.0f + erff(x * 0.7071067811865475f));
}

// ------------------------- setup kernels -----------------------------------
__global__ void cb_count(const int* __restrict__ subj) {
    __shared__ int c[NSUBJ];
    int tid = threadIdx.x;
    if (tid < NSUBJ) c[tid] = 0;
    __syncthreads();
    atomicAdd(&c[subj[tid]], 1);
    __syncthreads();
    if (tid < NSUBJ) g_cnt[tid] = c[tid];
}
// Fused init: zero stats, zero pad rows (hA stride-272, hB stride-320),
// transpose+convert w0 -> g_w fp16.
__global__ void cb_init(const float* __restrict__ w0) {
    int i = blockIdx.x * blockDim.x + threadIdx.x;
    const int n0 = 2 * NSUBJ * CH;
    const int n1 = BATCH * 4 * 272;
    const int n2 = BATCH * 4 * 320;
    const int n3 = CH * 832;
    if (i < n0) {
        if (i < NSUBJ * CH) g_sum[i] = 0.f; else g_sumsq[i - NSUBJ * CH] = 0.f;
        return;
    }
    i -= n0;
    if (i < n1) {
        int c = i % 272, rr = (i / 272) & 3, b = i / (4 * 272);
        int row = rr ? 512 + rr : 0;
        g_hA[((size_t)b * PADROWS + row) * 272 + c] = __float2half_rn(0.f);
        return;
    }
    i -= n1;
    if (i < n2) {
        int c = i % 320, rr = (i / 320) & 3, b = i / (4 * 320);
        int row = rr ? 512 + rr : 0;
        g_hB[((size_t)b * PADROWS + row) * 320 + c] = __float2half_rn(0.f);
        return;
    }
    i -= n2;
    if (i < n3) {
        int k = i % 832, co = i / 832;
        int tap = k / 272, ci = k % 272;
        float v = 0.f;
        if (tap < 3 && ci < CIN0) v = w0[((size_t)co * CIN0 + ci) * 3 + tap];
        g_w[(size_t)co * 832 + k] = __float2half_rn(v);
    }
}
// X [b][ci][t] fp32 -> g_hA padded NTC fp16 [b][t+1][272] (col 271 zero)
__global__ void cb_xT(const float* __restrict__ X, __half* __restrict__ dst) {
    __shared__ float tile[32][33];
    int lx = threadIdx.x, ly = threadIdx.y;
    int t0 = blockIdx.x * 32, c0 = blockIdx.y * 32, b = blockIdx.z;
#pragma unroll
    for (int i = 0; i < 4; i++) {
        int ci = c0 + ly + i * 8;
        float v = (ci < CIN0) ? X[((size_t)b * CIN0 + ci) * TLEN + t0 + lx] : 0.f;
        tile[ly + i * 8][lx] = v;
    }
    __syncthreads();
#pragma unroll
    for (int i = 0; i < 4; i++) {
        int tr = ly + i * 8;
        int ci = c0 + lx;
        if (ci < 272)
            dst[((size_t)b * PADROWS + t0 + tr + 1) * 272 + ci] =
                __float2half_rn(tile[lx][tr]);
    }
}
// Fused per-layer bookkeeping: finalize scale/shift (+zero stats), optional
// transpose of next layer's weights into g_w, optional pad-row zeroing of the
// next conv's output buffer (stride-320).
__global__ void cb_fin(const float* __restrict__ gamma,
                       const float* __restrict__ beta,
                       const float* __restrict__ wnext,   // may be null
                       __half* __restrict__ padbuf)        // may be null
{
    int i = blockIdx.x * blockDim.x + threadIdx.x;
    const int n0 = NSUBJ * CH;
    const int n1 = CH * 960;
    const int n2 = BATCH * 4 * 320;
    if (i < n0) {
        int s = i / CH;
        float cnt  = fmaxf((float)g_cnt[s] * (float)TLEN, 1.0f);
        float mean = g_sum[i] / cnt;
        float var  = g_sumsq[i] / cnt - mean * mean;
        float sc   = gamma[i] * rsqrtf(var + EPSV);
        g_scale[i] = sc;
        g_shift[i] = beta[i] - mean * sc;
        g_sum[i] = 0.f;
        g_sumsq[i] = 0.f;
        return;
    }
    i -= n0;
    if (i < n1) {
        if (wnext) {
            int k = i % 960, co = i / 960;
            int tap = k / CH, ci = k % CH;
            g_w[i] = __float2half_rn(wnext[((size_t)co * CH + ci) * 3 + tap]);
        }
        return;
    }
    i -= n1;
    if (i < n2 && padbuf) {
        int c = i % 320, rr = (i / 320) & 3, b = i / (4 * 320);
        int row = rr ? 512 + rr : 0;
        padbuf[((size_t)b * PADROWS + row) * 320 + c] = __float2half_rn(0.f);
    }
}
// in-place BN+GELU on padded NTC half buffer rows 1..512; 8 halves per thread.
__global__ void cb_bn_gelu(__half* __restrict__ buf, const int* __restrict__ subj) {
    int i = blockIdx.x * blockDim.x + threadIdx.x;
    const int PER_B = 512 * 40;           // 40 uint4 per 320-ch row
    if (i >= BATCH * PER_B) return;
    int b = i / PER_B;
    int rem = i - b * PER_B;
    int r = rem / 40, c4 = rem - r * 40;
    int s = subj[b];
    const float* scb = g_scale + s * CH + c4 * 8;
    const float* shb = g_shift + s * CH + c4 * 8;
    float4 sc0 = *(const float4*)scb, sc1 = *(const float4*)(scb + 4);
    float4 sh0 = *(const float4*)shb, sh1 = *(const float4*)(shb + 4);
    uint4* p = (uint4*)buf + ((size_t)b * PADROWS + r + 1) * 40 + c4;
    uint4 v = *p;
    __half2* h = (__half2*)&v;
    float2 f0 = __half22float2(h[0]);
    float2 f1 = __half22float2(h[1]);
    float2 f2 = __half22float2(h[2]);
    float2 f3 = __half22float2(h[3]);
    f0.x = gelu_f(fmaf(f0.x, sc0.x, sh0.x));
    f0.y = gelu_f(fmaf(f0.y, sc0.y, sh0.y));
    f1.x = gelu_f(fmaf(f1.x, sc0.z, sh0.z));
    f1.y = gelu_f(fmaf(f1.y, sc0.w, sh0.w));
    f2.x = gelu_f(fmaf(f2.x, sc1.x, sh1.x));
    f2.y = gelu_f(fmaf(f2.y, sc1.y, sh1.y));
    f3.x = gelu_f(fmaf(f3.x, sc1.z, sh1.z));
    f3.y = gelu_f(fmaf(f3.y, sc1.w, sh1.w));
    h[0] = __floats2half2_rn(f0.x, f0.y);
    h[1] = __floats2half2_rn(f1.x, f1.y);
    h[2] = __floats2half2_rn(f2.x, f2.y);
    h[3] = __floats2half2_rn(f3.x, f3.y);
    *p = v;
}
// final: BN+GELU + NTC->NCT transpose into d_out (fp32)
__global__ void cb_out(const __half* __restrict__ buf, const int* __restrict__ subj,
                       float* __restrict__ out) {
    __shared__ float tile[32][33];
    int lx = threadIdx.x, ly = threadIdx.y;
    int t0 = blockIdx.x * 32, c0 = blockIdx.y * 32, b = blockIdx.z;
    int s = subj[b];
    float sc = g_scale[s * CH + c0 + lx];
    float sh = g_shift[s * CH + c0 + lx];
#pragma unroll
    for (int i = 0; i < 4; i++) {
        int tr = ly + i * 8;
        float v = __half2float(buf[((size_t)b * PADROWS + t0 + tr + 1) * CH + c0 + lx]);
        tile[tr][lx] = gelu_f(fmaf(v, sc, sh));
    }
    __syncthreads();
#pragma unroll
    for (int i = 0; i < 4; i++) {
        int cr = ly + i * 8;
        out[((size_t)b * CH + c0 + cr) * TLEN + t0 + lx] = tile[lx][cr];
    }
}

// ------------------------- conv GEMM via mma.sync fp16 + ldmatrix ----------
// A: padded NTC half (row stride CSTRIDE halves). B: g_w [CH][KPAD] half.
// Block: 128 t-rows x 160 co, 256 threads, warp grid 2m x 4n (warp tile 64x40).
// grid = (4 t, 2 co, 256 b) = 2048 blocks, 2 CTAs/SM.
// K-chunk 64 (two k32 sub-chunks per ONE __syncthreads), 3-stage cp.async
// pipeline. 128B rows with XOR-swizzle (seg ^ (row&7)) — no pad, conflict-free.
// Inner loop: preload 5 B-frags (reused by all 4 mf), then per-mf A-frags.
#define TILE_N 160
#define NSTAGE 3
#define A_STG_B (128 * 128)         // bytes per stage
#define B_STG_B (TILE_N * 128)
#define CONV_SMEM (NSTAGE * (A_STG_B + B_STG_B))   // 110592
template <int KPAD, int CSTRIDE, bool RES>
__global__ void __launch_bounds__(256, 2) cb_conv(
    const __half* __restrict__ in, const __half* __restrict__ wts,
    const float* __restrict__ bias, const int* __restrict__ subj,
    __half* __restrict__ out)
{
    extern __shared__ char smc[];
    const uint32_t aB = smem_u32(smc);
    const uint32_t bB = aB + NSTAGE * A_STG_B;

    const int tid = threadIdx.x;
    const int wid = tid >> 5, lane = tid & 31;
    const int g = lane >> 2, tig = lane & 3;
    const int wm = wid & 1, wn = wid >> 1;      // 2m x 4n
    const int b = blockIdx.z, coBase = blockIdx.y * TILE_N, tBlk = blockIdx.x * 128;
    constexpr int NC = KPAD / 64;

    const __half* Ag = in + ((size_t)b * PADROWS + tBlk) * CSTRIDE;
    const __half* Wg = wts + (size_t)coBase * KPAD;

    // ldmatrix per-lane constants
    const int arow = wm * 64 + (lane & 15);        // mf adds +16 rows (2048 B)
    const uint32_t aRowB = aB + arow * 128;
    const uint32_t aswz = (uint32_t)(arow & 7) << 4;   // mf*16 ≡ 0 mod 8
    const int ah = lane >> 4;                      // 0/1 (k-half selector)
    const int brow = wn * 40 + (lane & 7);
    const uint32_t bRowB = bB + brow * 128;
    const uint32_t bswz = (uint32_t)(brow & 7) << 4;
    const int bj = (lane >> 3) & 3;                // matrix index 0..3

    // async-copy one 64-k (128B/row) chunk into stage (c % NSTAGE)
    auto issue = [&](int c) {
        const int st = c % NSTAGE;
        const uint32_t ao = aB + st * A_STG_B;
        const uint32_t bo = bB + st * B_STG_B;
        // A: 128 rows x 8 16B segs = 1024 ops (4/thread)
#pragma unroll
        for (int it = 0; it < 4; it++) {
            int idx = tid + it * 256;
            int row = idx >> 3, j = idx & 7;
            cpasync16(ao + row * 128 + ((uint32_t)(j ^ (row & 7)) << 4),
                      Ag + (size_t)row * CSTRIDE + c * 64 + j * 8);
        }
        // B: 160 rows x 8 segs = 1280 ops (5/thread)
#pragma unroll
        for (int it = 0; it < 5; it++) {
            int idx = tid + it * 256;
            int row = idx >> 3, j = idx & 7;
            cpasync16(bo + row * 128 + ((uint32_t)(j ^ (row & 7)) << 4),
                      Wg + (size_t)row * KPAD + c * 64 + j * 8);
        }
    };

    float acc[4][5][4];
#pragma unroll
    for (int mf = 0; mf < 4; mf++)
#pragma unroll
        for (int nf = 0; nf < 5; nf++)
#pragma unroll
            for (int j = 0; j < 4; j++) acc[mf][nf][j] = 0.f;

    issue(0); CP_COMMIT();
    issue(1); CP_COMMIT();
    for (int c = 0; c < NC; c++) {
        if (c + 1 < NC) CP_WAIT1(); else CP_WAIT0();
        __syncthreads();
        if (c + 2 < NC) { issue(c + 2); CP_COMMIT(); }
        const uint32_t aSt = (c % NSTAGE) * A_STG_B;
        const uint32_t bSt = (c % NSTAGE) * B_STG_B;

        // two k32 sub-chunks, one barrier
#pragma unroll
        for (int h2 = 0; h2 < 2; h2++) {
            // B fragments for all 5 nf (reused across 4 mf groups)
            const uint32_t bSeg = (uint32_t)(h2 * 4 + bj) << 4;
            const uint32_t bAddr0 = bRowB + bSt + (bSeg ^ bswz);
            uint32_t bf[5][4];
#pragma unroll
            for (int nf = 0; nf < 5; nf++)
                LDSM_X4(bf[nf][0], bf[nf][1], bf[nf][2], bf[nf][3],
                        bAddr0 + nf * 1024);
#pragma unroll
            for (int mf = 0; mf < 4; mf++) {
                uint32_t af[2][4];
#pragma unroll
                for (int ks = 0; ks < 2; ks++) {
                    uint32_t seg = (uint32_t)(h2 * 4 + ks * 2 + ah) << 4;
                    LDSM_X4(af[ks][0], af[ks][1], af[ks][2], af[ks][3],
                            aRowB + aSt + mf * 2048 + (seg ^ aswz));
                }
#pragma unroll
                for (int ks = 0; ks < 2; ks++)
#pragma unroll
                    for (int nf = 0; nf < 5; nf++)
                        mma_f16(acc[mf][nf], af[ks],
                                bf[nf][2 * ks], bf[nf][2 * ks + 1]);
            }
        }
    }

    // Epilogue: bias (+res), store NTC fp16, fused per-subject stats (fp32).
    const int sbj = subj[b];
#pragma unroll
    for (int nf = 0; nf < 5; nf++) {
        const int co = coBase + wn * 40 + nf * 8 + 2 * tig;
        const float bv0 = __ldg(bias + co), bv1 = __ldg(bias + co + 1);
        float s0 = 0.f, s1 = 0.f, q0 = 0.f, q1 = 0.f;
#pragma unroll
        for (int mf = 0; mf < 4; mf++) {
            const int trow = tBlk + wm * 64 + mf * 16 + g + 1;
            float y0 = acc[mf][nf][0] + bv0, y1 = acc[mf][nf][1] + bv1;
            float y2 = acc[mf][nf][2] + bv0, y3 = acc[mf][nf][3] + bv1;
            if (RES) {
                float2 r0 = __half22float2(
                    *(const __half2*)(in + ((size_t)b * PADROWS + trow) * CSTRIDE + co));
                float2 r1 = __half22float2(
                    *(const __half2*)(in + ((size_t)b * PADROWS + trow + 8) * CSTRIDE + co));
                y0 += r0.x; y1 += r0.y; y2 += r1.x; y3 += r1.y;
            }
            *(__half2*)(out + ((size_t)b * PADROWS + trow) * CH + co) =
                __floats2half2_rn(y0, y1);
            *(__half2*)(out + ((size_t)b * PADROWS + trow + 8) * CH + co) =
                __floats2half2_rn(y2, y3);
            s0 += y0 + y2; s1 += y1 + y3;
            q0 += y0 * y0 + y2 * y2; q1 += y1 * y1 + y3 * y3;
        }
#pragma unroll
        for (int off = 16; off >= 4; off >>= 1) {
            s0 += __shfl_down_sync(0xffffffffu, s0, off);
            s1 += __shfl_down_sync(0xffffffffu, s1, off);
            q0 += __shfl_down_sync(0xffffffffu, q0, off);
            q1 += __shfl_down_sync(0xffffffffu, q1, off);
        }
        if (lane < 4) {
            atomicAdd(&g_sum[sbj * CH + co], s0);
            atomicAdd(&g_sum[sbj * CH + co + 1], s1);
            atomicAdd(&g_sumsq[sbj * CH + co], q0);
            atomicAdd(&g_sumsq[sbj * CH + co + 1], q1);
        }
    }
}

// ---------------------------------------------------------------------------
extern "C" void kernel_launch(void* const* d_in, const int* in_sizes, int n_in,
                              void* d_out, int out_size) {
    const float* X    = (const float*)d_in[0];
    const int*   subj = (const int*)  d_in[1];
    const float* w0   = (const float*)d_in[2];
    const float* b0   = (const float*)d_in[3];
    const float* w1   = (const float*)d_in[4];
    const float* b1   = (const float*)d_in[5];
    const float* w2   = (const float*)d_in[6];
    const float* b2   = (const float*)d_in[7];
    const float* g0   = (const float*)d_in[8];
    const float* be0  = (const float*)d_in[9];
    const float* g1   = (const float*)d_in[10];
    const float* be1  = (const float*)d_in[11];
    const float* g2   = (const float*)d_in[12];
    const float* be2  = (const float*)d_in[13];
    float* out = (float*)d_out;
    (void)in_sizes; (void)n_in; (void)out_size;

    __half *pA, *pB, *pW;
    cudaGetSymbolAddress((void**)&pA, g_hA);
    cudaGetSymbolAddress((void**)&pB, g_hB);
    cudaGetSymbolAddress((void**)&pW, g_w);

    cudaFuncSetAttribute((const void*)cb_conv<832, 272, false>,
                         cudaFuncAttributeMaxDynamicSharedMemorySize, CONV_SMEM);
    cudaFuncSetAttribute((const void*)cb_conv<960, 320, true>,
                         cudaFuncAttributeMaxDynamicSharedMemorySize, CONV_SMEM);

    const dim3 cgrid(4, 2, BATCH);
    const int initN = 2 * NSUBJ * CH + BATCH * 4 * 272 + BATCH * 4 * 320 + CH * 832;
    const int finN  = NSUBJ * CH + CH * 960 + BATCH * 4 * 320;
    const int fingrid = (finN + 255) / 256;
    const int bngrid = (BATCH * 512 * 40 + 255) / 256;

    // ---- setup (conv0 lands at launch index 3 for ncu capture) ----
    cb_count<<<1, BATCH>>>(subj);                                   // 0
    cb_init<<<(initN + 511) / 512, 512>>>(w0);                      // 1
    cb_xT<<<dim3(16, 9, BATCH), dim3(32, 8)>>>(X, pA);              // 2

    // ---- layer 0: conv0(hA) -> hB ----
    cb_conv<832, 272, false><<<cgrid, 256, CONV_SMEM>>>(pA, pW, b0, subj, pB); // 3
    cb_fin<<<fingrid, 256>>>(g0, be0, w1, pA);   // finalize0 + tw(w1) + hA pads
    cb_bn_gelu<<<bngrid, 256>>>(pB, subj);

    // ---- layer 1: conv1(hB)+res -> hA ----
    cb_conv<960, 320, true><<<cgrid, 256, CONV_SMEM>>>(pB, pW, b1, subj, pA);
    cb_fin<<<fingrid, 256>>>(g1, be1, w2, (__half*)nullptr);  // finalize1 + tw(w2)
    cb_bn_gelu<<<bngrid, 256>>>(pA, subj);

    // ---- layer 2: conv2(hA)+res -> hB ----
    cb_conv<960, 320, true><<<cgrid, 256, CONV_SMEM>>>(pA, pW, b2, subj, pB);
    cb_fin<<<fingrid, 256>>>(g2, be2, (const float*)nullptr, (__half*)nullptr);
    cb_out<<<dim3(16, 10, BATCH), dim3(32, 8)>>>(pB, subj, out);
}

// round 15
// speedup vs baseline: 1.4379x; 1.0025x over previous
#include <cuda_runtime.h>
#include <cuda_fp16.h>
#include <math.h>
#include <stdint.h>

#define BATCH 256
#define TLEN  512
#define CIN0  271
#define CH    320
#define NSUBJ 4
#define EPSV  1e-5f
#define PADROWS 516

// ---------------- scratch (__device__ globals; no allocs allowed) ----------
__device__ __align__(16) __half g_hA[(size_t)BATCH * PADROWS * CH];  // 84.5 MB
__device__ __align__(16) __half g_hB[(size_t)BATCH * PADROWS * CH];  // 84.5 MB
__device__ __align__(16) __half g_w[CH * 960];   // [co][KPAD] fp16
__device__ float g_sum[NSUBJ * CH];
__device__ float g_sumsq[NSUBJ * CH];
__device__ float g_scale[NSUBJ * CH];
__device__ float g_shift[NSUBJ * CH];
__device__ int   g_cnt[NSUBJ];

// ---------------- helpers ---------------------------------------------------
__device__ __forceinline__ uint32_t smem_u32(const void* p) {
    uint32_t a;
    asm("{ .reg .u64 t; cvta.to.shared.u64 t, %1; cvt.u32.u64 %0, t; }"
        : "=r"(a) : "l"(p));
    return a;
}
__device__ __forceinline__ void cpasync16(uint32_t s, const void* g) {
    asm volatile("cp.async.cg.shared.global [%0], [%1], 16;" :: "r"(s), "l"(g));
}
#define CP_COMMIT() asm volatile("cp.async.commit_group;" ::: "memory")
#define CP_WAIT1()  asm volatile("cp.async.wait_group 1;" ::: "memory")
#define CP_WAIT0()  asm volatile("cp.async.wait_group 0;" ::: "memory")

#define LDSM_X4(r0, r1, r2, r3, addr) \
    asm volatile("ldmatrix.sync.aligned.m8n8.x4.shared.b16 {%0,%1,%2,%3}, [%4];" \
                 : "=r"(r0), "=r"(r1), "=r"(r2), "=r"(r3) : "r"(addr))

__device__ __forceinline__ void mma_f16(float* d, const uint32_t* a,
                                        uint32_t b0, uint32_t b1) {
    asm volatile(
        "mma.sync.aligned.m16n8k16.row.col.f32.f16.f16.f32 "
        "{%0,%1,%2,%3}, {%4,%5,%6,%7}, {%8,%9}, {%0,%1,%2,%3};"
        : "+f"(d[0]), "+f"(d[1]), "+f"(d[2]), "+f"(d[3])
        : "r"(a[0]), "r"(a[1]), "r"(a[2]), "r"(a[3]), "r"(b0), "r"(b1));
}
__device__ __forceinline__ float gelu_f(float x) {
    return 0.5f * x * (1.0f + erff(x * 0.7071067811865475f));
}

// ------------------------- setup kernels -----------------------------------
__global__ void cb_count(const int* __restrict__ subj) {
    __shared__ int c[NSUBJ];
    int tid = threadIdx.x;
    if (tid < NSUBJ) c[tid] = 0;
    __syncthreads();
    atomicAdd(&c[subj[tid]], 1);
    __syncthreads();
    if (tid < NSUBJ) g_cnt[tid] = c[tid];
}
// Fused init: zero stats, zero pad rows (hA stride-272, hB stride-320),
// transpose+convert w0 -> g_w fp16.
__global__ void cb_init(const float* __restrict__ w0) {
    int i = blockIdx.x * blockDim.x + threadIdx.x;
    const int n0 = 2 * NSUBJ * CH;
    const int n1 = BATCH * 4 * 272;
    const int n2 = BATCH * 4 * 320;
    const int n3 = CH * 832;
    if (i < n0) {
        if (i < NSUBJ * CH) g_sum[i] = 0.f; else g_sumsq[i - NSUBJ * CH] = 0.f;
        return;
    }
    i -= n0;
    if (i < n1) {
        int c = i % 272, rr = (i / 272) & 3, b = i / (4 * 272);
        int row = rr ? 512 + rr : 0;
        g_hA[((size_t)b * PADROWS + row) * 272 + c] = __float2half_rn(0.f);
        return;
    }
    i -= n1;
    if (i < n2) {
        int c = i % 320, rr = (i / 320) & 3, b = i / (4 * 320);
        int row = rr ? 512 + rr : 0;
        g_hB[((size_t)b * PADROWS + row) * 320 + c] = __float2half_rn(0.f);
        return;
    }
    i -= n2;
    if (i < n3) {
        int k = i % 832, co = i / 832;
        int tap = k / 272, ci = k % 272;
        float v = 0.f;
        if (tap < 3 && ci < CIN0) v = w0[((size_t)co * CIN0 + ci) * 3 + tap];
        g_w[(size_t)co * 832 + k] = __float2half_rn(v);
    }
}
// X [b][ci][t] fp32 -> g_hA padded NTC fp16 [b][t+1][272] (col 271 zero).
// 32t x 64c tiles: fp32 loads 128B, __half2 stores 128B coalesced.
__global__ void cb_xT(const float* __restrict__ X, __half* __restrict__ dst) {
    __shared__ float tile[32][65];
    int lx = threadIdx.x, ly = threadIdx.y;       // (32, 8)
    int t0 = blockIdx.x * 32, c0 = blockIdx.y * 64, b = blockIdx.z;
#pragma unroll
    for (int i = 0; i < 8; i++) {
        int ci = c0 + ly + i * 8;
        float v = (ci < CIN0) ? X[((size_t)b * CIN0 + ci) * TLEN + t0 + lx] : 0.f;
        tile[lx][ly + i * 8] = v;
    }
    __syncthreads();
#pragma unroll
    for (int i = 0; i < 4; i++) {
        int tr = ly + i * 8;
        int ci = c0 + 2 * lx;
        if (ci < 272) {
            __half2 h = __floats2half2_rn(tile[tr][2 * lx], tile[tr][2 * lx + 1]);
            *(__half2*)(dst + ((size_t)b * PADROWS + t0 + tr + 1) * 272 + ci) = h;
        }
    }
}
// Fused per-layer bookkeeping: finalize scale/shift (+zero stats), optional
// transpose of next layer's weights into g_w, optional pad-row zeroing of the
// next conv's output buffer (stride-320).
__global__ void cb_fin(const float* __restrict__ gamma,
                       const float* __restrict__ beta,
                       const float* __restrict__ wnext,   // may be null
                       __half* __restrict__ padbuf)        // may be null
{
    int i = blockIdx.x * blockDim.x + threadIdx.x;
    const int n0 = NSUBJ * CH;
    const int n1 = CH * 960;
    const int n2 = BATCH * 4 * 320;
    if (i < n0) {
        int s = i / CH;
        float cnt  = fmaxf((float)g_cnt[s] * (float)TLEN, 1.0f);
        float mean = g_sum[i] / cnt;
        float var  = g_sumsq[i] / cnt - mean * mean;
        float sc   = gamma[i] * rsqrtf(var + EPSV);
        g_scale[i] = sc;
        g_shift[i] = beta[i] - mean * sc;
        g_sum[i] = 0.f;
        g_sumsq[i] = 0.f;
        return;
    }
    i -= n0;
    if (i < n1) {
        if (wnext) {
            int k = i % 960, co = i / 960;
            int tap = k / CH, ci = k % CH;
            g_w[i] = __float2half_rn(wnext[((size_t)co * CH + ci) * 3 + tap]);
        }
        return;
    }
    i -= n1;
    if (i < n2 && padbuf) {
        int c = i % 320, rr = (i / 320) & 3, b = i / (4 * 320);
        int row = rr ? 512 + rr : 0;
        padbuf[((size_t)b * PADROWS + row) * 320 + c] = __float2half_rn(0.f);
    }
}
// in-place BN+GELU on padded NTC half buffer rows 1..512; 8 halves per thread.
__global__ void cb_bn_gelu(__half* __restrict__ buf, const int* __restrict__ subj) {
    int i = blockIdx.x * blockDim.x + threadIdx.x;
    const int PER_B = 512 * 40;           // 40 uint4 per 320-ch row
    if (i >= BATCH * PER_B) return;
    int b = i / PER_B;
    int rem = i - b * PER_B;
    int r = rem / 40, c4 = rem - r * 40;
    int s = subj[b];
    const float* scb = g_scale + s * CH + c4 * 8;
    const float* shb = g_shift + s * CH + c4 * 8;
    float4 sc0 = *(const float4*)scb, sc1 = *(const float4*)(scb + 4);
    float4 sh0 = *(const float4*)shb, sh1 = *(const float4*)(shb + 4);
    uint4* p = (uint4*)buf + ((size_t)b * PADROWS + r + 1) * 40 + c4;
    uint4 v = *p;
    __half2* h = (__half2*)&v;
    float2 f0 = __half22float2(h[0]);
    float2 f1 = __half22float2(h[1]);
    float2 f2 = __half22float2(h[2]);
    float2 f3 = __half22float2(h[3]);
    f0.x = gelu_f(fmaf(f0.x, sc0.x, sh0.x));
    f0.y = gelu_f(fmaf(f0.y, sc0.y, sh0.y));
    f1.x = gelu_f(fmaf(f1.x, sc0.z, sh0.z));
    f1.y = gelu_f(fmaf(f1.y, sc0.w, sh0.w));
    f2.x = gelu_f(fmaf(f2.x, sc1.x, sh1.x));
    f2.y = gelu_f(fmaf(f2.y, sc1.y, sh1.y));
    f3.x = gelu_f(fmaf(f3.x, sc1.z, sh1.z));
    f3.y = gelu_f(fmaf(f3.y, sc1.w, sh1.w));
    h[0] = __floats2half2_rn(f0.x, f0.y);
    h[1] = __floats2half2_rn(f1.x, f1.y);
    h[2] = __floats2half2_rn(f2.x, f2.y);
    h[3] = __floats2half2_rn(f3.x, f3.y);
    *p = v;
}
// final: BN+GELU + NTC->NCT transpose into d_out (fp32).
// 32t x 64c tiles: __half2 reads 128B, fp32 writes 128B coalesced.
__global__ void cb_out(const __half* __restrict__ buf, const int* __restrict__ subj,
                       float* __restrict__ out) {
    __shared__ float tile[64][33];
    int lx = threadIdx.x, ly = threadIdx.y;       // (32, 8)
    int t0 = blockIdx.x * 32, c0 = blockIdx.y * 64, b = blockIdx.z;
    int s = subj[b];
    float2 sc = *(const float2*)(g_scale + s * CH + c0 + 2 * lx);
    float2 sh = *(const float2*)(g_shift + s * CH + c0 + 2 * lx);
#pragma unroll
    for (int i = 0; i < 4; i++) {
        int tr = ly + i * 8;
        __half2 v = *(const __half2*)(buf +
            ((size_t)b * PADROWS + t0 + tr + 1) * CH + c0 + 2 * lx);
        float2 f = __half22float2(v);
        tile[2 * lx][tr]     = gelu_f(fmaf(f.x, sc.x, sh.x));
        tile[2 * lx + 1][tr] = gelu_f(fmaf(f.y, sc.y, sh.y));
    }
    __syncthreads();
#pragma unroll
    for (int i = 0; i < 8; i++) {
        int cr = ly + i * 8;
        out[((size_t)b * CH + c0 + cr) * TLEN + t0 + lx] = tile[cr][lx];
    }
}

// ------------------------- conv GEMM via mma.sync fp16 + ldmatrix ----------
// A: padded NTC half (row stride CSTRIDE halves). B: g_w [CH][KPAD] half.
// Block: 128 t-rows x 160 co, 256 threads, warp grid 2m x 4n (warp tile 64x40).
// grid = (4 t, 2 co, 256 b) = 2048 blocks, 2 CTAs/SM.
// K-chunk 64 (two k32 sub-chunks per ONE __syncthreads), 3-stage cp.async
// pipeline. 128B rows with XOR-swizzle (seg ^ (row&7)) — no pad, conflict-free.
// Inner loop: preload 5 B-frags (reused by all 4 mf), then per-mf A-frags.
#define TILE_N 160
#define NSTAGE 3
#define A_STG_B (128 * 128)         // bytes per stage
#define B_STG_B (TILE_N * 128)
#define CONV_SMEM (NSTAGE * (A_STG_B + B_STG_B))   // 110592
template <int KPAD, int CSTRIDE, bool RES>
__global__ void __launch_bounds__(256, 2) cb_conv(
    const __half* __restrict__ in, const __half* __restrict__ wts,
    const float* __restrict__ bias, const int* __restrict__ subj,
    __half* __restrict__ out)
{
    extern __shared__ char smc[];
    const uint32_t aB = smem_u32(smc);
    const uint32_t bB = aB + NSTAGE * A_STG_B;

    const int tid = threadIdx.x;
    const int wid = tid >> 5, lane = tid & 31;
    const int g = lane >> 2, tig = lane & 3;
    const int wm = wid & 1, wn = wid >> 1;      // 2m x 4n
    const int b = blockIdx.z, coBase = blockIdx.y * TILE_N, tBlk = blockIdx.x * 128;
    constexpr int NC = KPAD / 64;

    const __half* Ag = in + ((size_t)b * PADROWS + tBlk) * CSTRIDE;
    const __half* Wg = wts + (size_t)coBase * KPAD;

    // ldmatrix per-lane constants
    const int arow = wm * 64 + (lane & 15);        // mf adds +16 rows (2048 B)
    const uint32_t aRowB = aB + arow * 128;
    const uint32_t aswz = (uint32_t)(arow & 7) << 4;   // mf*16 ≡ 0 mod 8
    const int ah = lane >> 4;                      // 0/1 (k-half selector)
    const int brow = wn * 40 + (lane & 7);
    const uint32_t bRowB = bB + brow * 128;
    const uint32_t bswz = (uint32_t)(brow & 7) << 4;
    const int bj = (lane >> 3) & 3;                // matrix index 0..3

    // async-copy one 64-k (128B/row) chunk into stage (c % NSTAGE)
    auto issue = [&](int c) {
        const int st = c % NSTAGE;
        const uint32_t ao = aB + st * A_STG_B;
        const uint32_t bo = bB + st * B_STG_B;
        // A: 128 rows x 8 16B segs = 1024 ops (4/thread)
#pragma unroll
        for (int it = 0; it < 4; it++) {
            int idx = tid + it * 256;
            int row = idx >> 3, j = idx & 7;
            cpasync16(ao + row * 128 + ((uint32_t)(j ^ (row & 7)) << 4),
                      Ag + (size_t)row * CSTRIDE + c * 64 + j * 8);
        }
        // B: 160 rows x 8 segs = 1280 ops (5/thread)
#pragma unroll
        for (int it = 0; it < 5; it++) {
            int idx = tid + it * 256;
            int row = idx >> 3, j = idx & 7;
            cpasync16(bo + row * 128 + ((uint32_t)(j ^ (row & 7)) << 4),
                      Wg + (size_t)row * KPAD + c * 64 + j * 8);
        }
    };

    float acc[4][5][4];
#pragma unroll
    for (int mf = 0; mf < 4; mf++)
#pragma unroll
        for (int nf = 0; nf < 5; nf++)
#pragma unroll
            for (int j = 0; j < 4; j++) acc[mf][nf][j] = 0.f;

    issue(0); CP_COMMIT();
    issue(1); CP_COMMIT();
    for (int c = 0; c < NC; c++) {
        if (c + 1 < NC) CP_WAIT1(); else CP_WAIT0();
        __syncthreads();
        if (c + 2 < NC) { issue(c + 2); CP_COMMIT(); }
        const uint32_t aSt = (c % NSTAGE) * A_STG_B;
        const uint32_t bSt = (c % NSTAGE) * B_STG_B;

        // two k32 sub-chunks, one barrier
#pragma unroll
        for (int h2 = 0; h2 < 2; h2++) {
            // B fragments for all 5 nf (reused across 4 mf groups)
            const uint32_t bSeg = (uint32_t)(h2 * 4 + bj) << 4;
            const uint32_t bAddr0 = bRowB + bSt + (bSeg ^ bswz);
            uint32_t bf[5][4];
#pragma unroll
            for (int nf = 0; nf < 5; nf++)
                LDSM_X4(bf[nf][0], bf[nf][1], bf[nf][2], bf[nf][3],
                        bAddr0 + nf * 1024);
#pragma unroll
            for (int mf = 0; mf < 4; mf++) {
                uint32_t af[2][4];
#pragma unroll
                for (int ks = 0; ks < 2; ks++) {
                    uint32_t seg = (uint32_t)(h2 * 4 + ks * 2 + ah) << 4;
                    LDSM_X4(af[ks][0], af[ks][1], af[ks][2], af[ks][3],
                            aRowB + aSt + mf * 2048 + (seg ^ aswz));
                }
#pragma unroll
                for (int ks = 0; ks < 2; ks++)
#pragma unroll
                    for (int nf = 0; nf < 5; nf++)
                        mma_f16(acc[mf][nf], af[ks],
                                bf[nf][2 * ks], bf[nf][2 * ks + 1]);
            }
        }
    }

    // Epilogue: bias (+res), store NTC fp16, fused per-subject stats (fp32).
    const int sbj = subj[b];
#pragma unroll
    for (int nf = 0; nf < 5; nf++) {
        const int co = coBase + wn * 40 + nf * 8 + 2 * tig;
        const float bv0 = __ldg(bias + co), bv1 = __ldg(bias + co + 1);
        float s0 = 0.f, s1 = 0.f, q0 = 0.f, q1 = 0.f;
#pragma unroll
        for (int mf = 0; mf < 4; mf++) {
            const int trow = tBlk + wm * 64 + mf * 16 + g + 1;
            float y0 = acc[mf][nf][0] + bv0, y1 = acc[mf][nf][1] + bv1;
            float y2 = acc[mf][nf][2] + bv0, y3 = acc[mf][nf][3] + bv1;
            if (RES) {
                float2 r0 = __half22float2(
                    *(const __half2*)(in + ((size_t)b * PADROWS + trow) * CSTRIDE + co));
                float2 r1 = __half22float2(
                    *(const __half2*)(in + ((size_t)b * PADROWS + trow + 8) * CSTRIDE + co));
                y0 += r0.x; y1 += r0.y; y2 += r1.x; y3 += r1.y;
            }
            *(__half2*)(out + ((size_t)b * PADROWS + trow) * CH + co) =
                __floats2half2_rn(y0, y1);
            *(__half2*)(out + ((size_t)b * PADROWS + trow + 8) * CH + co) =
                __floats2half2_rn(y2, y3);
            s0 += y0 + y2; s1 += y1 + y3;
            q0 += y0 * y0 + y2 * y2; q1 += y1 * y1 + y3 * y3;
        }
#pragma unroll
        for (int off = 16; off >= 4; off >>= 1) {
            s0 += __shfl_down_sync(0xffffffffu, s0, off);
            s1 += __shfl_down_sync(0xffffffffu, s1, off);
            q0 += __shfl_down_sync(0xffffffffu, q0, off);
            q1 += __shfl_down_sync(0xffffffffu, q1, off);
        }
        if (lane < 4) {
            atomicAdd(&g_sum[sbj * CH + co], s0);
            atomicAdd(&g_sum[sbj * CH + co + 1], s1);
            atomicAdd(&g_sumsq[sbj * CH + co], q0);
            atomicAdd(&g_sumsq[sbj * CH + co + 1], q1);
        }
    }
}

// ---------------------------------------------------------------------------
extern "C" void kernel_launch(void* const* d_in, const int* in_sizes, int n_in,
                              void* d_out, int out_size) {
    const float* X    = (const float*)d_in[0];
    const int*   subj = (const int*)  d_in[1];
    const float* w0   = (const float*)d_in[2];
    const float* b0   = (const float*)d_in[3];
    const float* w1   = (const float*)d_in[4];
    const float* b1   = (const float*)d_in[5];
    const float* w2   = (const float*)d_in[6];
    const float* b2   = (const float*)d_in[7];
    const float* g0   = (const float*)d_in[8];
    const float* be0  = (const float*)d_in[9];
    const float* g1   = (const float*)d_in[10];
    const float* be1  = (const float*)d_in[11];
    const float* g2   = (const float*)d_in[12];
    const float* be2  = (const float*)d_in[13];
    float* out = (float*)d_out;
    (void)in_sizes; (void)n_in; (void)out_size;

    __half *pA, *pB, *pW;
    cudaGetSymbolAddress((void**)&pA, g_hA);
    cudaGetSymbolAddress((void**)&pB, g_hB);
    cudaGetSymbolAddress((void**)&pW, g_w);

    cudaFuncSetAttribute((const void*)cb_conv<832, 272, false>,
                         cudaFuncAttributeMaxDynamicSharedMemorySize, CONV_SMEM);
    cudaFuncSetAttribute((const void*)cb_conv<960, 320, true>,
                         cudaFuncAttributeMaxDynamicSharedMemorySize, CONV_SMEM);

    const dim3 cgrid(4, 2, BATCH);
    const int initN = 2 * NSUBJ * CH + BATCH * 4 * 272 + BATCH * 4 * 320 + CH * 832;
    const int finN  = NSUBJ * CH + CH * 960 + BATCH * 4 * 320;
    const int fingrid = (finN + 255) / 256;
    const int bngrid = (BATCH * 512 * 40 + 255) / 256;

    // ---- setup (conv0 lands at launch index 3 for ncu capture) ----
    cb_count<<<1, BATCH>>>(subj);                                   // 0
    cb_init<<<(initN + 511) / 512, 512>>>(w0);                      // 1
    cb_xT<<<dim3(16, 5, BATCH), dim3(32, 8)>>>(X, pA);              // 2

    // ---- layer 0: conv0(hA) -> hB ----
    cb_conv<832, 272, false><<<cgrid, 256, CONV_SMEM>>>(pA, pW, b0, subj, pB); // 3
    cb_fin<<<fingrid, 256>>>(g0, be0, w1, pA);   // finalize0 + tw(w1) + hA pads
    cb_bn_gelu<<<bngrid, 256>>>(pB, subj);

    // ---- layer 1: conv1(hB)+res -> hA ----
    cb_conv<960, 320, true><<<cgrid, 256, CONV_SMEM>>>(pB, pW, b1, subj, pA);
    cb_fin<<<fingrid, 256>>>(g1, be1, w2, (__half*)nullptr);  // finalize1 + tw(w2)
    cb_bn_gelu<<<bngrid, 256>>>(pA, subj);

    // ---- layer 2: conv2(hA)+res -> hB ----
    cb_conv<960, 320, true><<<cgrid, 256, CONV_SMEM>>>(pA, pW, b2, subj, pB);
    cb_fin<<<fingrid, 256>>>(g2, be2, (const float*)nullptr, (__half*)nullptr);
    cb_out<<<dim3(16, 5, BATCH), dim3(32, 8)>>>(pB, subj, out);
}

// round 16
// speedup vs baseline: 1.4571x; 1.0134x over previous
#include <cuda_runtime.h>
#include <cuda_fp16.h>
#include <math.h>
#include <stdint.h>

#define BATCH 256
#define TLEN  512
#define CIN0  271
#define CH    320
#define NSUBJ 4
#define EPSV  1e-5f
#define PADROWS 516

// ---------------- scratch (__device__ globals; no allocs allowed) ----------
__device__ __align__(16) __half g_hA[(size_t)BATCH * PADROWS * CH];  // 84.5 MB
__device__ __align__(16) __half g_hB[(size_t)BATCH * PADROWS * CH];  // 84.5 MB
__device__ __align__(16) __half g_w0[CH * 832];   // [co][KPAD] fp16
__device__ __align__(16) __half g_w1[CH * 960];
__device__ __align__(16) __half g_w2[CH * 960];
__device__ float g_sum[NSUBJ * CH];
__device__ float g_sumsq[NSUBJ * CH];
__device__ float g_scale[NSUBJ * CH];
__device__ float g_shift[NSUBJ * CH];
__device__ int   g_cnt[NSUBJ];

// ---------------- helpers ---------------------------------------------------
__device__ __forceinline__ uint32_t smem_u32(const void* p) {
    uint32_t a;
    asm("{ .reg .u64 t; cvta.to.shared.u64 t, %1; cvt.u32.u64 %0, t; }"
        : "=r"(a) : "l"(p));
    return a;
}
__device__ __forceinline__ void cpasync16(uint32_t s, const void* g) {
    asm volatile("cp.async.cg.shared.global [%0], [%1], 16;" :: "r"(s), "l"(g));
}
#define CP_COMMIT() asm volatile("cp.async.commit_group;" ::: "memory")
#define CP_WAIT1()  asm volatile("cp.async.wait_group 1;" ::: "memory")
#define CP_WAIT0()  asm volatile("cp.async.wait_group 0;" ::: "memory")

#define LDSM_X4(r0, r1, r2, r3, addr) \
    asm volatile("ldmatrix.sync.aligned.m8n8.x4.shared.b16 {%0,%1,%2,%3}, [%4];" \
                 : "=r"(r0), "=r"(r1), "=r"(r2), "=r"(r3) : "r"(addr))

__device__ __forceinline__ void mma_f16(float* d, const uint32_t* a,
                                        uint32_t b0, uint32_t b1) {
    asm volatile(
        "mma.sync.aligned.m16n8k16.row.col.f32.f16.f16.f32 "
        "{%0,%1,%2,%3}, {%4,%5,%6,%7}, {%8,%9}, {%0,%1,%2,%3};"
        : "+f"(d[0]), "+f"(d[1]), "+f"(d[2]), "+f"(d[3])
        : "r"(a[0]), "r"(a[1]), "r"(a[2]), "r"(a[3]), "r"(b0), "r"(b1));
}
__device__ __forceinline__ float gelu_f(float x) {
    return 0.5f * x * (1.0f + erff(x * 0.7071067811865475f));
}

// ------------------------- setup kernels -----------------------------------
__global__ void cb_count(const int* __restrict__ subj) {
    __shared__ int c[NSUBJ];
    int tid = threadIdx.x;
    if (tid < NSUBJ) c[tid] = 0;
    __syncthreads();
    atomicAdd(&c[subj[tid]], 1);
    __syncthreads();
    if (tid < NSUBJ) g_cnt[tid] = c[tid];
}
// Fused init: zero stats, zero pad rows (hA stride-272, hB stride-320),
// transpose+convert w0/w1/w2 -> g_w0/g_w1/g_w2 fp16.
__global__ void cb_init(const float* __restrict__ w0,
                        const float* __restrict__ w1,
                        const float* __restrict__ w2) {
    int i = blockIdx.x * blockDim.x + threadIdx.x;
    const int n0 = 2 * NSUBJ * CH;
    const int n1 = BATCH * 4 * 272;
    const int n2 = BATCH * 4 * 320;
    const int n3 = CH * 832;
    const int n4 = CH * 960;
    if (i < n0) {
        if (i < NSUBJ * CH) g_sum[i] = 0.f; else g_sumsq[i - NSUBJ * CH] = 0.f;
        return;
    }
    i -= n0;
    if (i < n1) {
        int c = i % 272, rr = (i / 272) & 3, b = i / (4 * 272);
        int row = rr ? 512 + rr : 0;
        g_hA[((size_t)b * PADROWS + row) * 272 + c] = __float2half_rn(0.f);
        return;
    }
    i -= n1;
    if (i < n2) {
        int c = i % 320, rr = (i / 320) & 3, b = i / (4 * 320);
        int row = rr ? 512 + rr : 0;
        g_hB[((size_t)b * PADROWS + row) * 320 + c] = __float2half_rn(0.f);
        return;
    }
    i -= n2;
    if (i < n3) {
        int k = i % 832, co = i / 832;
        int tap = k / 272, ci = k % 272;
        float v = 0.f;
        if (tap < 3 && ci < CIN0) v = w0[((size_t)co * CIN0 + ci) * 3 + tap];
        g_w0[(size_t)co * 832 + k] = __float2half_rn(v);
        return;
    }
    i -= n3;
    if (i < n4) {
        int k = i % 960, co = i / 960;
        int tap = k / CH, ci = k % CH;
        g_w1[i] = __float2half_rn(w1[((size_t)co * CH + ci) * 3 + tap]);
        return;
    }
    i -= n4;
    if (i < n4) {
        int k = i % 960, co = i / 960;
        int tap = k / CH, ci = k % CH;
        g_w2[i] = __float2half_rn(w2[((size_t)co * CH + ci) * 3 + tap]);
    }
}
// X [b][ci][t] fp32 -> g_hA padded NTC fp16 [b][t+1][272] (col 271 zero).
__global__ void cb_xT(const float* __restrict__ X, __half* __restrict__ dst) {
    __shared__ float tile[32][65];
    int lx = threadIdx.x, ly = threadIdx.y;       // (32, 8)
    int t0 = blockIdx.x * 32, c0 = blockIdx.y * 64, b = blockIdx.z;
#pragma unroll
    for (int i = 0; i < 8; i++) {
        int ci = c0 + ly + i * 8;
        float v = (ci < CIN0) ? X[((size_t)b * CIN0 + ci) * TLEN + t0 + lx] : 0.f;
        tile[lx][ly + i * 8] = v;
    }
    __syncthreads();
#pragma unroll
    for (int i = 0; i < 4; i++) {
        int tr = ly + i * 8;
        int ci = c0 + 2 * lx;
        if (ci < 272) {
            __half2 h = __floats2half2_rn(tile[tr][2 * lx], tile[tr][2 * lx + 1]);
            *(__half2*)(dst + ((size_t)b * PADROWS + t0 + tr + 1) * 272 + ci) = h;
        }
    }
}
// finalize scale/shift (+zero stats); optional pad-row zeroing of the next
// conv's output buffer (stride-320). Weight transposes moved to cb_init.
__global__ void cb_fin(const float* __restrict__ gamma,
                       const float* __restrict__ beta,
                       __half* __restrict__ padbuf)        // may be null
{
    int i = blockIdx.x * blockDim.x + threadIdx.x;
    const int n0 = NSUBJ * CH;
    const int n2 = BATCH * 4 * 320;
    if (i < n0) {
        int s = i / CH;
        float cnt  = fmaxf((float)g_cnt[s] * (float)TLEN, 1.0f);
        float mean = g_sum[i] / cnt;
        float var  = g_sumsq[i] / cnt - mean * mean;
        float sc   = gamma[i] * rsqrtf(var + EPSV);
        g_scale[i] = sc;
        g_shift[i] = beta[i] - mean * sc;
        g_sum[i] = 0.f;
        g_sumsq[i] = 0.f;
        return;
    }
    i -= n0;
    if (i < n2 && padbuf) {
        int c = i % 320, rr = (i / 320) & 3, b = i / (4 * 320);
        int row = rr ? 512 + rr : 0;
        padbuf[((size_t)b * PADROWS + row) * 320 + c] = __float2half_rn(0.f);
    }
}
// in-place BN+GELU on padded NTC half buffer rows 1..512; 8 halves per thread.
__global__ void cb_bn_gelu(__half* __restrict__ buf, const int* __restrict__ subj) {
    int i = blockIdx.x * blockDim.x + threadIdx.x;
    const int PER_B = 512 * 40;           // 40 uint4 per 320-ch row
    if (i >= BATCH * PER_B) return;
    int b = i / PER_B;
    int rem = i - b * PER_B;
    int r = rem / 40, c4 = rem - r * 40;
    int s = subj[b];
    const float* scb = g_scale + s * CH + c4 * 8;
    const float* shb = g_shift + s * CH + c4 * 8;
    float4 sc0 = *(const float4*)scb, sc1 = *(const float4*)(scb + 4);
    float4 sh0 = *(const float4*)shb, sh1 = *(const float4*)(shb + 4);
    uint4* p = (uint4*)buf + ((size_t)b * PADROWS + r + 1) * 40 + c4;
    uint4 v = *p;
    __half2* h = (__half2*)&v;
    float2 f0 = __half22float2(h[0]);
    float2 f1 = __half22float2(h[1]);
    float2 f2 = __half22float2(h[2]);
    float2 f3 = __half22float2(h[3]);
    f0.x = gelu_f(fmaf(f0.x, sc0.x, sh0.x));
    f0.y = gelu_f(fmaf(f0.y, sc0.y, sh0.y));
    f1.x = gelu_f(fmaf(f1.x, sc0.z, sh0.z));
    f1.y = gelu_f(fmaf(f1.y, sc0.w, sh0.w));
    f2.x = gelu_f(fmaf(f2.x, sc1.x, sh1.x));
    f2.y = gelu_f(fmaf(f2.y, sc1.y, sh1.y));
    f3.x = gelu_f(fmaf(f3.x, sc1.z, sh1.z));
    f3.y = gelu_f(fmaf(f3.y, sc1.w, sh1.w));
    h[0] = __floats2half2_rn(f0.x, f0.y);
    h[1] = __floats2half2_rn(f1.x, f1.y);
    h[2] = __floats2half2_rn(f2.x, f2.y);
    h[3] = __floats2half2_rn(f3.x, f3.y);
    *p = v;
}
// final: BN+GELU + NTC->NCT transpose into d_out (fp32).
__global__ void cb_out(const __half* __restrict__ buf, const int* __restrict__ subj,
                       float* __restrict__ out) {
    __shared__ float tile[64][33];
    int lx = threadIdx.x, ly = threadIdx.y;       // (32, 8)
    int t0 = blockIdx.x * 32, c0 = blockIdx.y * 64, b = blockIdx.z;
    int s = subj[b];
    float2 sc = *(const float2*)(g_scale + s * CH + c0 + 2 * lx);
    float2 sh = *(const float2*)(g_shift + s * CH + c0 + 2 * lx);
#pragma unroll
    for (int i = 0; i < 4; i++) {
        int tr = ly + i * 8;
        __half2 v = *(const __half2*)(buf +
            ((size_t)b * PADROWS + t0 + tr + 1) * CH + c0 + 2 * lx);
        float2 f = __half22float2(v);
        tile[2 * lx][tr]     = gelu_f(fmaf(f.x, sc.x, sh.x));
        tile[2 * lx + 1][tr] = gelu_f(fmaf(f.y, sc.y, sh.y));
    }
    __syncthreads();
#pragma unroll
    for (int i = 0; i < 8; i++) {
        int cr = ly + i * 8;
        out[((size_t)b * CH + c0 + cr) * TLEN + t0 + lx] = tile[cr][lx];
    }
}

// ------------------------- conv GEMM via mma.sync fp16 + ldmatrix ----------
// A: padded NTC half (row stride CSTRIDE halves). B: g_w* [CH][KPAD] half.
// Block: 128 t-rows x 160 co, 256 threads, warp grid 2m x 4n (warp tile 64x40).
// grid = (4 t, 2 co, 256 b) = 2048 blocks, 2 CTAs/SM.
// K-chunk 64 (two k32 sub-chunks per ONE __syncthreads), 3-stage cp.async
// pipeline. 128B rows with XOR-swizzle (seg ^ (row&7)) — no pad, conflict-free.
// Inner loop: preload 5 B-frags (reused by all 4 mf), then per-mf A-frags.
#define TILE_N 160
#define NSTAGE 3
#define A_STG_B (128 * 128)         // bytes per stage
#define B_STG_B (TILE_N * 128)
#define CONV_SMEM (NSTAGE * (A_STG_B + B_STG_B))   // 110592
template <int KPAD, int CSTRIDE, bool RES>
__global__ void __launch_bounds__(256, 2) cb_conv(
    const __half* __restrict__ in, const __half* __restrict__ wts,
    const float* __restrict__ bias, const int* __restrict__ subj,
    __half* __restrict__ out)
{
    extern __shared__ char smc[];
    const uint32_t aB = smem_u32(smc);
    const uint32_t bB = aB + NSTAGE * A_STG_B;

    const int tid = threadIdx.x;
    const int wid = tid >> 5, lane = tid & 31;
    const int g = lane >> 2, tig = lane & 3;
    const int wm = wid & 1, wn = wid >> 1;      // 2m x 4n
    const int b = blockIdx.z, coBase = blockIdx.y * TILE_N, tBlk = blockIdx.x * 128;
    constexpr int NC = KPAD / 64;

    const __half* Ag = in + ((size_t)b * PADROWS + tBlk) * CSTRIDE;
    const __half* Wg = wts + (size_t)coBase * KPAD;

    // ldmatrix per-lane constants
    const int arow = wm * 64 + (lane & 15);        // mf adds +16 rows (2048 B)
    const uint32_t aRowB = aB + arow * 128;
    const uint32_t aswz = (uint32_t)(arow & 7) << 4;   // mf*16 ≡ 0 mod 8
    const int ah = lane >> 4;                      // 0/1 (k-half selector)
    const int brow = wn * 40 + (lane & 7);
    const uint32_t bRowB = bB + brow * 128;
    const uint32_t bswz = (uint32_t)(brow & 7) << 4;
    const int bj = (lane >> 3) & 3;                // matrix index 0..3

    // async-copy one 64-k (128B/row) chunk into stage (c % NSTAGE)
    auto issue = [&](int c) {
        const int st = c % NSTAGE;
        const uint32_t ao = aB + st * A_STG_B;
        const uint32_t bo = bB + st * B_STG_B;
        // A: 128 rows x 8 16B segs = 1024 ops (4/thread)
#pragma unroll
        for (int it = 0; it < 4; it++) {
            int idx = tid + it * 256;
            int row = idx >> 3, j = idx & 7;
            cpasync16(ao + row * 128 + ((uint32_t)(j ^ (row & 7)) << 4),
                      Ag + (size_t)row * CSTRIDE + c * 64 + j * 8);
        }
        // B: 160 rows x 8 segs = 1280 ops (5/thread)
#pragma unroll
        for (int it = 0; it < 5; it++) {
            int idx = tid + it * 256;
            int row = idx >> 3, j = idx & 7;
            cpasync16(bo + row * 128 + ((uint32_t)(j ^ (row & 7)) << 4),
                      Wg + (size_t)row * KPAD + c * 64 + j * 8);
        }
    };

    float acc[4][5][4];
#pragma unroll
    for (int mf = 0; mf < 4; mf++)
#pragma unroll
        for (int nf = 0; nf < 5; nf++)
#pragma unroll
            for (int j = 0; j < 4; j++) acc[mf][nf][j] = 0.f;

    issue(0); CP_COMMIT();
    issue(1); CP_COMMIT();
    for (int c = 0; c < NC; c++) {
        if (c + 1 < NC) CP_WAIT1(); else CP_WAIT0();
        __syncthreads();
        if (c + 2 < NC) { issue(c + 2); CP_COMMIT(); }
        const uint32_t aSt = (c % NSTAGE) * A_STG_B;
        const uint32_t bSt = (c % NSTAGE) * B_STG_B;

        // two k32 sub-chunks, one barrier
#pragma unroll
        for (int h2 = 0; h2 < 2; h2++) {
            // B fragments for all 5 nf (reused across 4 mf groups)
            const uint32_t bSeg = (uint32_t)(h2 * 4 + bj) << 4;
            const uint32_t bAddr0 = bRowB + bSt + (bSeg ^ bswz);
            uint32_t bf[5][4];
#pragma unroll
            for (int nf = 0; nf < 5; nf++)
                LDSM_X4(bf[nf][0], bf[nf][1], bf[nf][2], bf[nf][3],
                        bAddr0 + nf * 1024);
#pragma unroll
            for (int mf = 0; mf < 4; mf++) {
                uint32_t af[2][4];
#pragma unroll
                for (int ks = 0; ks < 2; ks++) {
                    uint32_t seg = (uint32_t)(h2 * 4 + ks * 2 + ah) << 4;
                    LDSM_X4(af[ks][0], af[ks][1], af[ks][2], af[ks][3],
                            aRowB + aSt + mf * 2048 + (seg ^ aswz));
                }
#pragma unroll
                for (int ks = 0; ks < 2; ks++)
#pragma unroll
                    for (int nf = 0; nf < 5; nf++)
                        mma_f16(acc[mf][nf], af[ks],
                                bf[nf][2 * ks], bf[nf][2 * ks + 1]);
            }
        }
    }

    // Epilogue: bias (+res), store NTC fp16, fused per-subject stats (fp32).
    const int sbj = subj[b];
#pragma unroll
    for (int nf = 0; nf < 5; nf++) {
        const int co = coBase + wn * 40 + nf * 8 + 2 * tig;
        const float bv0 = __ldg(bias + co), bv1 = __ldg(bias + co + 1);
        float s0 = 0.f, s1 = 0.f, q0 = 0.f, q1 = 0.f;
#pragma unroll
        for (int mf = 0; mf < 4; mf++) {
            const int trow = tBlk + wm * 64 + mf * 16 + g + 1;
            float y0 = acc[mf][nf][0] + bv0, y1 = acc[mf][nf][1] + bv1;
            float y2 = acc[mf][nf][2] + bv0, y3 = acc[mf][nf][3] + bv1;
            if (RES) {
                float2 r0 = __half22float2(
                    *(const __half2*)(in + ((size_t)b * PADROWS + trow) * CSTRIDE + co));
                float2 r1 = __half22float2(
                    *(const __half2*)(in + ((size_t)b * PADROWS + trow + 8) * CSTRIDE + co));
                y0 += r0.x; y1 += r0.y; y2 += r1.x; y3 += r1.y;
            }
            *(__half2*)(out + ((size_t)b * PADROWS + trow) * CH + co) =
                __floats2half2_rn(y0, y1);
            *(__half2*)(out + ((size_t)b * PADROWS + trow + 8) * CH + co) =
                __floats2half2_rn(y2, y3);
            s0 += y0 + y2; s1 += y1 + y3;
            q0 += y0 * y0 + y2 * y2; q1 += y1 * y1 + y3 * y3;
        }
#pragma unroll
        for (int off = 16; off >= 4; off >>= 1) {
            s0 += __shfl_down_sync(0xffffffffu, s0, off);
            s1 += __shfl_down_sync(0xffffffffu, s1, off);
            q0 += __shfl_down_sync(0xffffffffu, q0, off);
            q1 += __shfl_down_sync(0xffffffffu, q1, off);
        }
        if (lane < 4) {
            atomicAdd(&g_sum[sbj * CH + co], s0);
            atomicAdd(&g_sum[sbj * CH + co + 1], s1);
            atomicAdd(&g_sumsq[sbj * CH + co], q0);
            atomicAdd(&g_sumsq[sbj * CH + co + 1], q1);
        }
    }
}

// ---------------------------------------------------------------------------
extern "C" void kernel_launch(void* const* d_in, const int* in_sizes, int n_in,
                              void* d_out, int out_size) {
    const float* X    = (const float*)d_in[0];
    const int*   subj = (const int*)  d_in[1];
    const float* w0   = (const float*)d_in[2];
    const float* b0   = (const float*)d_in[3];
    const float* w1   = (const float*)d_in[4];
    const float* b1   = (const float*)d_in[5];
    const float* w2   = (const float*)d_in[6];
    const float* b2   = (const float*)d_in[7];
    const float* g0   = (const float*)d_in[8];
    const float* be0  = (const float*)d_in[9];
    const float* g1   = (const float*)d_in[10];
    const float* be1  = (const float*)d_in[11];
    const float* g2   = (const float*)d_in[12];
    const float* be2  = (const float*)d_in[13];
    float* out = (float*)d_out;
    (void)in_sizes; (void)n_in; (void)out_size;

    __half *pA, *pB, *pW0, *pW1, *pW2;
    cudaGetSymbolAddress((void**)&pA, g_hA);
    cudaGetSymbolAddress((void**)&pB, g_hB);
    cudaGetSymbolAddress((void**)&pW0, g_w0);
    cudaGetSymbolAddress((void**)&pW1, g_w1);
    cudaGetSymbolAddress((void**)&pW2, g_w2);

    cudaFuncSetAttribute((const void*)cb_conv<832, 272, false>,
                         cudaFuncAttributeMaxDynamicSharedMemorySize, CONV_SMEM);
    cudaFuncSetAttribute((const void*)cb_conv<960, 320, true>,
                         cudaFuncAttributeMaxDynamicSharedMemorySize, CONV_SMEM);

    const dim3 cgrid(4, 2, BATCH);
    const int initN = 2 * NSUBJ * CH + BATCH * 4 * 272 + BATCH * 4 * 320
                    + CH * 832 + 2 * CH * 960;
    const int finPadN  = NSUBJ * CH + BATCH * 4 * 320;
    const int finN     = NSUBJ * CH;
    const int bngrid = (BATCH * 512 * 40 + 255) / 256;

    // ---- setup (conv0 lands at launch index 3 for ncu capture) ----
    cb_count<<<1, BATCH>>>(subj);                                   // 0
    cb_init<<<(initN + 511) / 512, 512>>>(w0, w1, w2);              // 1
    cb_xT<<<dim3(16, 5, BATCH), dim3(32, 8)>>>(X, pA);              // 2

    // ---- layer 0: conv0(hA) -> hB ----
    cb_conv<832, 272, false><<<cgrid, 256, CONV_SMEM>>>(pA, pW0, b0, subj, pB); // 3
    cb_fin<<<(finPadN + 255) / 256, 256>>>(g0, be0, pA);   // finalize0 + hA pads
    cb_bn_gelu<<<bngrid, 256>>>(pB, subj);

    // ---- layer 1: conv1(hB)+res -> hA ----
    cb_conv<960, 320, true><<<cgrid, 256, CONV_SMEM>>>(pB, pW1, b1, subj, pA);
    cb_fin<<<(finN + 255) / 256, 256>>>(g1, be1, (__half*)nullptr);
    cb_bn_gelu<<<bngrid, 256>>>(pA, subj);

    // ---- layer 2: conv2(hA)+res -> hB ----
    cb_conv<960, 320, true><<<cgrid, 256, CONV_SMEM>>>(pA, pW2, b2, subj, pB);
    cb_fin<<<(finN + 255) / 256, 256>>>(g2, be2, (__half*)nullptr);
    cb_out<<<dim3(16, 5, BATCH), dim3(32, 8)>>>(pB, subj, out);
}

// round 17
// speedup vs baseline: 1.4591x; 1.0014x over previous
#include <cuda_runtime.h>
#include <cuda_fp16.h>
#include <math.h>
#include <stdint.h>

#define BATCH 256
#define TLEN  512
#define CIN0  271
#define CH    320
#define NSUBJ 4
#define EPSV  1e-5f
#define PADROWS 516

// ---------------- scratch (__device__ globals; no allocs allowed) ----------
__device__ __align__(16) __half g_hA[(size_t)BATCH * PADROWS * CH];  // 84.5 MB
__device__ __align__(16) __half g_hB[(size_t)BATCH * PADROWS * CH];  // 84.5 MB
__device__ __align__(16) __half g_w0[CH * 832];   // [co][KPAD] fp16
__device__ __align__(16) __half g_w1[CH * 960];
__device__ __align__(16) __half g_w2[CH * 960];
__device__ float g_sum[NSUBJ * CH];
__device__ float g_sumsq[NSUBJ * CH];
__device__ float g_scale[NSUBJ * CH];
__device__ float g_shift[NSUBJ * CH];
__device__ int   g_cnt[NSUBJ];

// ---------------- helpers ---------------------------------------------------
__device__ __forceinline__ uint32_t smem_u32(const void* p) {
    uint32_t a;
    asm("{ .reg .u64 t; cvta.to.shared.u64 t, %1; cvt.u32.u64 %0, t; }"
        : "=r"(a) : "l"(p));
    return a;
}
__device__ __forceinline__ void cpasync16(uint32_t s, const void* g) {
    asm volatile("cp.async.cg.shared.global [%0], [%1], 16;" :: "r"(s), "l"(g));
}
#define CP_COMMIT() asm volatile("cp.async.commit_group;" ::: "memory")
#define CP_WAIT1()  asm volatile("cp.async.wait_group 1;" ::: "memory")
#define CP_WAIT0()  asm volatile("cp.async.wait_group 0;" ::: "memory")

#define LDSM_X4(r0, r1, r2, r3, addr) \
    asm volatile("ldmatrix.sync.aligned.m8n8.x4.shared.b16 {%0,%1,%2,%3}, [%4];" \
                 : "=r"(r0), "=r"(r1), "=r"(r2), "=r"(r3) : "r"(addr))

__device__ __forceinline__ void mma_f16(float* d, const uint32_t* a,
                                        uint32_t b0, uint32_t b1) {
    asm volatile(
        "mma.sync.aligned.m16n8k16.row.col.f32.f16.f16.f32 "
        "{%0,%1,%2,%3}, {%4,%5,%6,%7}, {%8,%9}, {%0,%1,%2,%3};"
        : "+f"(d[0]), "+f"(d[1]), "+f"(d[2]), "+f"(d[3])
        : "r"(a[0]), "r"(a[1]), "r"(a[2]), "r"(a[3]), "r"(b0), "r"(b1));
}
__device__ __forceinline__ float gelu_f(float x) {
    return 0.5f * x * (1.0f + erff(x * 0.7071067811865475f));
}

// ------------------------- setup kernels -----------------------------------
// Fused init: subject counts (block 0), zero stats, zero pad rows
// (hA stride-272, hB stride-320), transpose+convert w0/w1/w2 fp16.
__global__ void cb_init(const float* __restrict__ w0,
                        const float* __restrict__ w1,
                        const float* __restrict__ w2,
                        const int* __restrict__ subj) {
    if (blockIdx.x == 0) {
        __shared__ int c[NSUBJ];
        if (threadIdx.x < NSUBJ) c[threadIdx.x] = 0;
        __syncthreads();
        if (threadIdx.x < BATCH) atomicAdd(&c[subj[threadIdx.x]], 1);
        __syncthreads();
        if (threadIdx.x < NSUBJ) g_cnt[threadIdx.x] = c[threadIdx.x];
    }
    int i = blockIdx.x * blockDim.x + threadIdx.x;
    const int n0 = 2 * NSUBJ * CH;
    const int n1 = BATCH * 4 * 272;
    const int n2 = BATCH * 4 * 320;
    const int n3 = CH * 832;
    const int n4 = CH * 960;
    if (i < n0) {
        if (i < NSUBJ * CH) g_sum[i] = 0.f; else g_sumsq[i - NSUBJ * CH] = 0.f;
        return;
    }
    i -= n0;
    if (i < n1) {
        int c = i % 272, rr = (i / 272) & 3, b = i / (4 * 272);
        int row = rr ? 512 + rr : 0;
        g_hA[((size_t)b * PADROWS + row) * 272 + c] = __float2half_rn(0.f);
        return;
    }
    i -= n1;
    if (i < n2) {
        int c = i % 320, rr = (i / 320) & 3, b = i / (4 * 320);
        int row = rr ? 512 + rr : 0;
        g_hB[((size_t)b * PADROWS + row) * 320 + c] = __float2half_rn(0.f);
        return;
    }
    i -= n2;
    if (i < n3) {
        int k = i % 832, co = i / 832;
        int tap = k / 272, ci = k % 272;
        float v = 0.f;
        if (tap < 3 && ci < CIN0) v = w0[((size_t)co * CIN0 + ci) * 3 + tap];
        g_w0[(size_t)co * 832 + k] = __float2half_rn(v);
        return;
    }
    i -= n3;
    if (i < n4) {
        int k = i % 960, co = i / 960;
        int tap = k / CH, ci = k % CH;
        g_w1[i] = __float2half_rn(w1[((size_t)co * CH + ci) * 3 + tap]);
        return;
    }
    i -= n4;
    if (i < n4) {
        int k = i % 960, co = i / 960;
        int tap = k / CH, ci = k % CH;
        g_w2[i] = __float2half_rn(w2[((size_t)co * CH + ci) * 3 + tap]);
    }
}
// X [b][ci][t] fp32 -> g_hA padded NTC fp16 [b][t+1][272] (col 271 zero).
__global__ void cb_xT(const float* __restrict__ X, __half* __restrict__ dst) {
    __shared__ float tile[32][65];
    int lx = threadIdx.x, ly = threadIdx.y;       // (32, 8)
    int t0 = blockIdx.x * 32, c0 = blockIdx.y * 64, b = blockIdx.z;
#pragma unroll
    for (int i = 0; i < 8; i++) {
        int ci = c0 + ly + i * 8;
        float v = (ci < CIN0) ? X[((size_t)b * CIN0 + ci) * TLEN + t0 + lx] : 0.f;
        tile[lx][ly + i * 8] = v;
    }
    __syncthreads();
#pragma unroll
    for (int i = 0; i < 4; i++) {
        int tr = ly + i * 8;
        int ci = c0 + 2 * lx;
        if (ci < 272) {
            __half2 h = __floats2half2_rn(tile[tr][2 * lx], tile[tr][2 * lx + 1]);
            *(__half2*)(dst + ((size_t)b * PADROWS + t0 + tr + 1) * 272 + ci) = h;
        }
    }
}
// finalize scale/shift (+zero stats for next layer). 1280 threads.
__global__ void cb_fin(const float* __restrict__ gamma,
                       const float* __restrict__ beta)
{
    int i = blockIdx.x * blockDim.x + threadIdx.x;
    if (i >= NSUBJ * CH) return;
    int s = i / CH;
    float cnt  = fmaxf((float)g_cnt[s] * (float)TLEN, 1.0f);
    float mean = g_sum[i] / cnt;
    float var  = g_sumsq[i] / cnt - mean * mean;
    float sc   = gamma[i] * rsqrtf(var + EPSV);
    g_scale[i] = sc;
    g_shift[i] = beta[i] - mean * sc;
    g_sum[i] = 0.f;
    g_sumsq[i] = 0.f;
}
// in-place BN+GELU on padded NTC half buffer rows 1..512; 8 halves per thread.
// Tail blocks (optional) zero the pad rows of padbuf (stride-320 buffer).
__global__ void cb_bn_gelu(__half* __restrict__ buf, const int* __restrict__ subj,
                           __half* __restrict__ padbuf) {
    int i = blockIdx.x * blockDim.x + threadIdx.x;
    const int PER_B = 512 * 40;           // 40 uint4 per 320-ch row
    if (i >= BATCH * PER_B) {
        int j = i - BATCH * PER_B;        // uint4 index into pad region
        if (padbuf && j < BATCH * 4 * 40) {
            int c4 = j % 40, rr = (j / 40) & 3, b = j / 160;
            int row = rr ? 512 + rr : 0;
            ((uint4*)padbuf)[((size_t)b * PADROWS + row) * 40 + c4] =
                make_uint4(0u, 0u, 0u, 0u);
        }
        return;
    }
    int b = i / PER_B;
    int rem = i - b * PER_B;
    int r = rem / 40, c4 = rem - r * 40;
    int s = subj[b];
    const float* scb = g_scale + s * CH + c4 * 8;
    const float* shb = g_shift + s * CH + c4 * 8;
    float4 sc0 = *(const float4*)scb, sc1 = *(const float4*)(scb + 4);
    float4 sh0 = *(const float4*)shb, sh1 = *(const float4*)(shb + 4);
    uint4* p = (uint4*)buf + ((size_t)b * PADROWS + r + 1) * 40 + c4;
    uint4 v = *p;
    __half2* h = (__half2*)&v;
    float2 f0 = __half22float2(h[0]);
    float2 f1 = __half22float2(h[1]);
    float2 f2 = __half22float2(h[2]);
    float2 f3 = __half22float2(h[3]);
    f0.x = gelu_f(fmaf(f0.x, sc0.x, sh0.x));
    f0.y = gelu_f(fmaf(f0.y, sc0.y, sh0.y));
    f1.x = gelu_f(fmaf(f1.x, sc0.z, sh0.z));
    f1.y = gelu_f(fmaf(f1.y, sc0.w, sh0.w));
    f2.x = gelu_f(fmaf(f2.x, sc1.x, sh1.x));
    f2.y = gelu_f(fmaf(f2.y, sc1.y, sh1.y));
    f3.x = gelu_f(fmaf(f3.x, sc1.z, sh1.z));
    f3.y = gelu_f(fmaf(f3.y, sc1.w, sh1.w));
    h[0] = __floats2half2_rn(f0.x, f0.y);
    h[1] = __floats2half2_rn(f1.x, f1.y);
    h[2] = __floats2half2_rn(f2.x, f2.y);
    h[3] = __floats2half2_rn(f3.x, f3.y);
    *p = v;
}
// final: BN+GELU + NTC->NCT transpose into d_out (fp32).
__global__ void cb_out(const __half* __restrict__ buf, const int* __restrict__ subj,
                       float* __restrict__ out) {
    __shared__ float tile[64][33];
    int lx = threadIdx.x, ly = threadIdx.y;       // (32, 8)
    int t0 = blockIdx.x * 32, c0 = blockIdx.y * 64, b = blockIdx.z;
    int s = subj[b];
    float2 sc = *(const float2*)(g_scale + s * CH + c0 + 2 * lx);
    float2 sh = *(const float2*)(g_shift + s * CH + c0 + 2 * lx);
#pragma unroll
    for (int i = 0; i < 4; i++) {
        int tr = ly + i * 8;
        __half2 v = *(const __half2*)(buf +
            ((size_t)b * PADROWS + t0 + tr + 1) * CH + c0 + 2 * lx);
        float2 f = __half22float2(v);
        tile[2 * lx][tr]     = gelu_f(fmaf(f.x, sc.x, sh.x));
        tile[2 * lx + 1][tr] = gelu_f(fmaf(f.y, sc.y, sh.y));
    }
    __syncthreads();
#pragma unroll
    for (int i = 0; i < 8; i++) {
        int cr = ly + i * 8;
        out[((size_t)b * CH + c0 + cr) * TLEN + t0 + lx] = tile[cr][lx];
    }
}

// ------------------------- conv GEMM via mma.sync fp16 + ldmatrix ----------
// A: padded NTC half (row stride CSTRIDE halves). B: g_w* [CH][KPAD] half.
// Block: 128 t-rows x 160 co, 256 threads, warp grid 2m x 4n (warp tile 64x40).
// grid = (4 t, 2 co, 256 b) = 2048 blocks, 2 CTAs/SM.
// K-chunk 64 (two k32 sub-chunks per ONE __syncthreads), 3-stage cp.async
// pipeline. 128B rows with XOR-swizzle (seg ^ (row&7)) — no pad, conflict-free.
// Inner loop: preload 5 B-frags (reused by all 4 mf), then per-mf A-frags.
#define TILE_N 160
#define NSTAGE 3
#define A_STG_B (128 * 128)         // bytes per stage
#define B_STG_B (TILE_N * 128)
#define CONV_SMEM (NSTAGE * (A_STG_B + B_STG_B))   // 110592
template <int KPAD, int CSTRIDE, bool RES>
__global__ void __launch_bounds__(256, 2) cb_conv(
    const __half* __restrict__ in, const __half* __restrict__ wts,
    const float* __restrict__ bias, const int* __restrict__ subj,
    __half* __restrict__ out)
{
    extern __shared__ char smc[];
    const uint32_t aB = smem_u32(smc);
    const uint32_t bB = aB + NSTAGE * A_STG_B;

    const int tid = threadIdx.x;
    const int wid = tid >> 5, lane = tid & 31;
    const int g = lane >> 2, tig = lane & 3;
    const int wm = wid & 1, wn = wid >> 1;      // 2m x 4n
    const int b = blockIdx.z, coBase = blockIdx.y * TILE_N, tBlk = blockIdx.x * 128;
    constexpr int NC = KPAD / 64;

    const __half* Ag = in + ((size_t)b * PADROWS + tBlk) * CSTRIDE;
    const __half* Wg = wts + (size_t)coBase * KPAD;

    // ldmatrix per-lane constants
    const int arow = wm * 64 + (lane & 15);        // mf adds +16 rows (2048 B)
    const uint32_t aRowB = aB + arow * 128;
    const uint32_t aswz = (uint32_t)(arow & 7) << 4;   // mf*16 ≡ 0 mod 8
    const int ah = lane >> 4;                      // 0/1 (k-half selector)
    const int brow = wn * 40 + (lane & 7);
    const uint32_t bRowB = bB + brow * 128;
    const uint32_t bswz = (uint32_t)(brow & 7) << 4;
    const int bj = (lane >> 3) & 3;                // matrix index 0..3

    // async-copy one 64-k (128B/row) chunk into stage (c % NSTAGE)
    auto issue = [&](int c) {
        const int st = c % NSTAGE;
        const uint32_t ao = aB + st * A_STG_B;
        const uint32_t bo = bB + st * B_STG_B;
        // A: 128 rows x 8 16B segs = 1024 ops (4/thread)
#pragma unroll
        for (int it = 0; it < 4; it++) {
            int idx = tid + it * 256;
            int row = idx >> 3, j = idx & 7;
            cpasync16(ao + row * 128 + ((uint32_t)(j ^ (row & 7)) << 4),
                      Ag + (size_t)row * CSTRIDE + c * 64 + j * 8);
        }
        // B: 160 rows x 8 segs = 1280 ops (5/thread)
#pragma unroll
        for (int it = 0; it < 5; it++) {
            int idx = tid + it * 256;
            int row = idx >> 3, j = idx & 7;
            cpasync16(bo + row * 128 + ((uint32_t)(j ^ (row & 7)) << 4),
                      Wg + (size_t)row * KPAD + c * 64 + j * 8);
        }
    };

    float acc[4][5][4];
#pragma unroll
    for (int mf = 0; mf < 4; mf++)
#pragma unroll
        for (int nf = 0; nf < 5; nf++)
#pragma unroll
            for (int j = 0; j < 4; j++) acc[mf][nf][j] = 0.f;

    issue(0); CP_COMMIT();
    issue(1); CP_COMMIT();
    for (int c = 0; c < NC; c++) {
        if (c + 1 < NC) CP_WAIT1(); else CP_WAIT0();
        __syncthreads();
        if (c + 2 < NC) { issue(c + 2); CP_COMMIT(); }
        const uint32_t aSt = (c % NSTAGE) * A_STG_B;
        const uint32_t bSt = (c % NSTAGE) * B_STG_B;

        // two k32 sub-chunks, one barrier
#pragma unroll
        for (int h2 = 0; h2 < 2; h2++) {
            // B fragments for all 5 nf (reused across 4 mf groups)
            const uint32_t bSeg = (uint32_t)(h2 * 4 + bj) << 4;
            const uint32_t bAddr0 = bRowB + bSt + (bSeg ^ bswz);
            uint32_t bf[5][4];
#pragma unroll
            for (int nf = 0; nf < 5; nf++)
                LDSM_X4(bf[nf][0], bf[nf][1], bf[nf][2], bf[nf][3],
                        bAddr0 + nf * 1024);
#pragma unroll
            for (int mf = 0; mf < 4; mf++) {
                uint32_t af[2][4];
#pragma unroll
                for (int ks = 0; ks < 2; ks++) {
                    uint32_t seg = (uint32_t)(h2 * 4 + ks * 2 + ah) << 4;
                    LDSM_X4(af[ks][0], af[ks][1], af[ks][2], af[ks][3],
                            aRowB + aSt + mf * 2048 + (seg ^ aswz));
                }
#pragma unroll
                for (int ks = 0; ks < 2; ks++)
#pragma unroll
                    for (int nf = 0; nf < 5; nf++)
                        mma_f16(acc[mf][nf], af[ks],
                                bf[nf][2 * ks], bf[nf][2 * ks + 1]);
            }
        }
    }

    // Epilogue: bias (+res), store NTC fp16, fused per-subject stats (fp32).
    const int sbj = subj[b];
#pragma unroll
    for (int nf = 0; nf < 5; nf++) {
        const int co = coBase + wn * 40 + nf * 8 + 2 * tig;
        const float bv0 = __ldg(bias + co), bv1 = __ldg(bias + co + 1);
        float s0 = 0.f, s1 = 0.f, q0 = 0.f, q1 = 0.f;
#pragma unroll
        for (int mf = 0; mf < 4; mf++) {
            const int trow = tBlk + wm * 64 + mf * 16 + g + 1;
            float y0 = acc[mf][nf][0] + bv0, y1 = acc[mf][nf][1] + bv1;
            float y2 = acc[mf][nf][2] + bv0, y3 = acc[mf][nf][3] + bv1;
            if (RES) {
                float2 r0 = __half22float2(
                    *(const __half2*)(in + ((size_t)b * PADROWS + trow) * CSTRIDE + co));
                float2 r1 = __half22float2(
                    *(const __half2*)(in + ((size_t)b * PADROWS + trow + 8) * CSTRIDE + co));
                y0 += r0.x; y1 += r0.y; y2 += r1.x; y3 += r1.y;
            }
            *(__half2*)(out + ((size_t)b * PADROWS + trow) * CH + co) =
                __floats2half2_rn(y0, y1);
            *(__half2*)(out + ((size_t)b * PADROWS + trow + 8) * CH + co) =
                __floats2half2_rn(y2, y3);
            s0 += y0 + y2; s1 += y1 + y3;
            q0 += y0 * y0 + y2 * y2; q1 += y1 * y1 + y3 * y3;
        }
#pragma unroll
        for (int off = 16; off >= 4; off >>= 1) {
            s0 += __shfl_down_sync(0xffffffffu, s0, off);
            s1 += __shfl_down_sync(0xffffffffu, s1, off);
            q0 += __shfl_down_sync(0xffffffffu, q0, off);
            q1 += __shfl_down_sync(0xffffffffu, q1, off);
        }
        if (lane < 4) {
            atomicAdd(&g_sum[sbj * CH + co], s0);
            atomicAdd(&g_sum[sbj * CH + co + 1], s1);
            atomicAdd(&g_sumsq[sbj * CH + co], q0);
            atomicAdd(&g_sumsq[sbj * CH + co + 1], q1);
        }
    }
}

// ---------------------------------------------------------------------------
extern "C" void kernel_launch(void* const* d_in, const int* in_sizes, int n_in,
                              void* d_out, int out_size) {
    const float* X    = (const float*)d_in[0];
    const int*   subj = (const int*)  d_in[1];
    const float* w0   = (const float*)d_in[2];
    const float* b0   = (const float*)d_in[3];
    const float* w1   = (const float*)d_in[4];
    const float* b1   = (const float*)d_in[5];
    const float* w2   = (const float*)d_in[6];
    const float* b2   = (const float*)d_in[7];
    const float* g0   = (const float*)d_in[8];
    const float* be0  = (const float*)d_in[9];
    const float* g1   = (const float*)d_in[10];
    const float* be1  = (const float*)d_in[11];
    const float* g2   = (const float*)d_in[12];
    const float* be2  = (const float*)d_in[13];
    float* out = (float*)d_out;
    (void)in_sizes; (void)n_in; (void)out_size;

    __half *pA, *pB, *pW0, *pW1, *pW2;
    cudaGetSymbolAddress((void**)&pA, g_hA);
    cudaGetSymbolAddress((void**)&pB, g_hB);
    cudaGetSymbolAddress((void**)&pW0, g_w0);
    cudaGetSymbolAddress((void**)&pW1, g_w1);
    cudaGetSymbolAddress((void**)&pW2, g_w2);

    cudaFuncSetAttribute((const void*)cb_conv<832, 272, false>,
                         cudaFuncAttributeMaxDynamicSharedMemorySize, CONV_SMEM);
    cudaFuncSetAttribute((const void*)cb_conv<960, 320, true>,
                         cudaFuncAttributeMaxDynamicSharedMemorySize, CONV_SMEM);

    const dim3 cgrid(4, 2, BATCH);
    const int initN = 2 * NSUBJ * CH + BATCH * 4 * 272 + BATCH * 4 * 320
                    + CH * 832 + 2 * CH * 960;
    const int finN  = NSUBJ * CH;
    const int bnN     = BATCH * 512 * 40;
    const int bnPadN  = bnN + BATCH * 4 * 40;      // + pad uint4s
    const int bngrid    = (bnN + 255) / 256;
    const int bnPadGrid = (bnPadN + 255) / 256;

    // ---- setup ----
    cb_init<<<(initN + 511) / 512, 512>>>(w0, w1, w2, subj);        // 0
    cb_xT<<<dim3(16, 5, BATCH), dim3(32, 8)>>>(X, pA);              // 1

    // ---- layer 0: conv0(hA) -> hB ----
    cb_conv<832, 272, false><<<cgrid, 256, CONV_SMEM>>>(pA, pW0, b0, subj, pB); // 2
    cb_fin<<<(finN + 255) / 256, 256>>>(g0, be0);                   // 3
    cb_bn_gelu<<<bnPadGrid, 256>>>(pB, subj, pA);   // bn(pB) + hA pad zeroing

    // ---- layer 1: conv1(hB)+res -> hA ----
    cb_conv<960, 320, true><<<cgrid, 256, CONV_SMEM>>>(pB, pW1, b1, subj, pA);
    cb_fin<<<(finN + 255) / 256, 256>>>(g1, be1);
    cb_bn_gelu<<<bngrid, 256>>>(pA, subj, (__half*)nullptr);

    // ---- layer 2: conv2(hA)+res -> hB ----
    cb_conv<960, 320, true><<<cgrid, 256, CONV_SMEM>>>(pA, pW2, b2, subj, pB);
    cb_fin<<<(finN + 255) / 256, 256>>>(g2, be2);
    cb_out<<<dim3(16, 5, BATCH), dim3(32, 8)>>>(pB, subj, out);
}